// round 10
// baseline (speedup 1.0000x reference)
#include <cuda_runtime.h>
#include <cuda_bf16.h>
#include <math.h>
#include <stdint.h>

#define NN    1024
#define NE    4096
#define D     256
#define HN    4
#define DHD   64
#define NODEK 512
#define EDGEK 2048
#define CLS   16
#define MAXC  1024

// mma.sync GEMM: CTA 128x64, K chunked (2 x 128), 8 warps (4m x 2n), warp 32x32
#define KC     128
#define APITCH 136
#define BPITCH 136
#define OFF_AHI 0
#define OFF_ALO (128 * APITCH)
#define OFF_BHI (2 * 128 * APITCH)
#define OFF_BLO (2 * 128 * APITCH + 64 * BPITCH)
#define MMA_SMEM_ELEMS (2 * 128 * APITCH + 2 * 64 * BPITCH)
#define MMA_SMEM_BYTES (MMA_SMEM_ELEMS * 2)   // 104448 B -> 2 CTAs/SM

// ---------------- scratch ----------------
__device__ float g_nscore[NN];
__device__ float g_escore[NE];
__device__ int   g_nmask[NN];
__device__ int   g_emask[NE];
__device__ int   g_src[NE], g_dst[NE];
__device__ int   g_off[NN + 1];
__device__ int   g_inc[2 * NE];
__device__ float g_q[NE * D];
__device__ float g_k[NE * D];
__device__ float g_v[NE * D];
// split-bf16 activations (hi + residual lo): same operands the MMA needs
__device__ __nv_bfloat16 g_hhi[NE * D],   g_hlo[NE * D];    // pair 0
__device__ __nv_bfloat16 g_aohi[NE * D],  g_aolo[NE * D];   // pair 1
__device__ __nv_bfloat16 g_ohi[NE * D],   g_olo[NE * D];    // pair 2
__device__ __nv_bfloat16 g_hidhi[NE * D], g_hidlo[NE * D];  // pair 3
// transposed split-bf16 weights: [w][n][k], w: 0=Wnp 1=Wq 2=Wk 3=Wv 4=Wo 5=W1
__device__ __nv_bfloat16 g_wthi[6 * D * D];
__device__ __nv_bfloat16 g_wtlo[6 * D * D];

template <int ID> __device__ __forceinline__ __nv_bfloat16* bufhi();
template <> __device__ __forceinline__ __nv_bfloat16* bufhi<0>() { return g_hhi; }
template <> __device__ __forceinline__ __nv_bfloat16* bufhi<1>() { return g_aohi; }
template <> __device__ __forceinline__ __nv_bfloat16* bufhi<2>() { return g_ohi; }
template <> __device__ __forceinline__ __nv_bfloat16* bufhi<3>() { return g_hidhi; }
template <int ID> __device__ __forceinline__ __nv_bfloat16* buflo();
template <> __device__ __forceinline__ __nv_bfloat16* buflo<0>() { return g_hlo; }
template <> __device__ __forceinline__ __nv_bfloat16* buflo<1>() { return g_aolo; }
template <> __device__ __forceinline__ __nv_bfloat16* buflo<2>() { return g_olo; }
template <> __device__ __forceinline__ __nv_bfloat16* buflo<3>() { return g_hidlo; }

// ================= 1: fused front-end =================
__global__ void k_front(const float* __restrict__ nf, const float* __restrict__ efi,
                        const int* __restrict__ ei,
                        const float* __restrict__ Wn, const float* __restrict__ bn,
                        const float* __restrict__ We, const float* __restrict__ be,
                        const float* __restrict__ Wnp, const float* __restrict__ Wq,
                        const float* __restrict__ Wk, const float* __restrict__ Wv,
                        const float* __restrict__ Wo, const float* __restrict__ W1) {
    int b = blockIdx.x;
    int tid = threadIdx.x;
    if (b < 96) {
        __shared__ float s[64][65];
        int w = b >> 4, t16 = b & 15;
        const float* W;
        switch (w) {
            case 0: W = Wnp; break;
            case 1: W = Wq; break;
            case 2: W = Wk; break;
            case 3: W = Wv; break;
            case 4: W = Wo; break;
            default: W = W1; break;
        }
        int n0 = (t16 & 3) * 64, k0 = (t16 >> 2) * 64;
        int n4 = (tid & 15) * 4, kr = tid >> 4;
        #pragma unroll
        for (int kk = kr; kk < 64; kk += 16) {
            float4 v = *(const float4*)&W[(size_t)(k0 + kk) * D + n0 + n4];
            s[kk][n4] = v.x;
            s[kk][n4 + 1] = v.y;
            s[kk][n4 + 2] = v.z;
            s[kk][n4 + 3] = v.w;
        }
        __syncthreads();
        int nl = tid >> 2, kq = (tid & 3) * 16;
        __nv_bfloat16 hi[16], lo[16];
        #pragma unroll
        for (int i = 0; i < 16; ++i) {
            float x = s[kq + i][nl];
            hi[i] = __float2bfloat16(x);
            lo[i] = __float2bfloat16(x - __bfloat162float(hi[i]));
        }
        size_t off = (size_t)w * D * D + (size_t)(n0 + nl) * D + k0 + kq;
        *(uint4*)&g_wthi[off] = *(uint4*)&hi[0];
        *(uint4*)&g_wthi[off + 8] = *(uint4*)&hi[8];
        *(uint4*)&g_wtlo[off] = *(uint4*)&lo[0];
        *(uint4*)&g_wtlo[off + 8] = *(uint4*)&lo[8];
    } else if (b < 112) {
        __shared__ int sh[256];
        int acc = 0;
        for (int i = tid; i < 2048; i += 256) acc |= ei[2 * i + 1];
        sh[tid] = acc;
        __syncthreads();
        for (int s2 = 128; s2 > 0; s2 >>= 1) {
            if (tid < s2) sh[tid] |= sh[tid + s2];
            __syncthreads();
        }
        int is64 = (sh[0] == 0) ? 1 : 0;
        int i = (b - 96) * 256 + tid;
        int s, d;
        if (is64) { s = ei[2 * i]; d = ei[2 * (NE + i)]; }
        else      { s = ei[i];     d = ei[NE + i]; }
        g_src[i] = s;
        g_dst[i] = d;
    } else {
        int warp = (b - 112) * 8 + (tid >> 5);
        int lane = tid & 31;
        const float* x;
        const float* w;
        if (warp < NN) { x = nf + (size_t)warp * D; w = Wn; }
        else           { x = efi + (size_t)(warp - NN) * D; w = We; }
        float s = 0.f;
        #pragma unroll
        for (int i = 0; i < D / 32; ++i) s += x[lane + i * 32] * w[lane + i * 32];
        #pragma unroll
        for (int o = 16; o; o >>= 1) s += __shfl_xor_sync(0xffffffffu, s, o);
        if (lane == 0) {
            if (warp < NN) g_nscore[warp] = s + bn[0];
            else           g_escore[warp - NN] = s + be[0];
        }
    }
}

// ================= 2: fused build =================
struct TkSmem {
    unsigned su[NE];
    int hist[256];
    unsigned pref;
    int krem;
    int wagg[32];
};
struct IncSmem {
    int cnt[NN];
    int off[NN];
    int pos[NN];
    int inc[2 * NE];
};
union BuildSmem {
    TkSmem tk;
    IncSmem in;
};

__global__ void __launch_bounds__(1024, 1) k_build() {
    __shared__ BuildSmem sm;
    int tid = threadIdx.x;
    int lane = tid & 31, wid = tid >> 5;

    if (blockIdx.x < 2) {
        const bool is_edge = (blockIdx.x == 1);
        const float* sc = is_edge ? g_escore : g_nscore;
        int* mask = is_edge ? g_emask : g_nmask;
        const int n = is_edge ? NE : NN;
        const int kk = is_edge ? EDGEK : NODEK;
        int items = n >> 10;

        for (int j = 0; j < items; ++j) {
            int i = tid * items + j;
            unsigned bb = __float_as_uint(sc[i]);
            sm.tk.su[i] = (bb & 0x80000000u) ? ~bb : (bb | 0x80000000u);
        }
        if (tid == 0) { sm.tk.pref = 0u; sm.tk.krem = kk; }
        __syncthreads();

        for (int shift = 24; shift >= 0; shift -= 8) {
            unsigned prefix = sm.tk.pref;
            unsigned done_mask = (shift == 24) ? 0u : (0xFFFFFFFFu << (shift + 8));
            if (tid < 256) sm.tk.hist[tid] = 0;
            __syncthreads();
            for (int j = 0; j < items; ++j) {
                unsigned u = sm.tk.su[tid * items + j];
                if ((u & done_mask) == prefix)
                    atomicAdd(&sm.tk.hist[(u >> shift) & 255], 1);
            }
            __syncthreads();
            if (wid == 0) {
                int krem = sm.tk.krem;
                int gsum = 0;
                #pragma unroll
                for (int c = 0; c < 8; ++c) gsum += sm.tk.hist[lane * 8 + c];
                int x = gsum;
                #pragma unroll
                for (int off = 1; off < 32; off <<= 1) {
                    int t = __shfl_down_sync(0xffffffffu, x, off);
                    if (lane + off < 32) x += t;
                }
                int above = x - gsum;
                bool hit = (above < krem) && (x >= krem);
                unsigned bal = __ballot_sync(0xffffffffu, hit);
                int srcl = __ffs(bal) - 1;
                if (lane == srcl) {
                    int cum = above;
                    #pragma unroll
                    for (int c = 7; c >= 0; --c) {
                        int bb = lane * 8 + c;
                        int hc = sm.tk.hist[bb];
                        if (cum + hc >= krem) {
                            sm.tk.pref = prefix | ((unsigned)bb << shift);
                            sm.tk.krem = krem - cum;
                            break;
                        }
                        cum += hc;
                    }
                }
            }
            __syncthreads();
        }
        unsigned T = sm.tk.pref;
        int r = sm.tk.krem;

        int ct = 0;
        for (int j = 0; j < items; ++j) ct += (sm.tk.su[tid * items + j] == T) ? 1 : 0;
        int scan = ct;
        #pragma unroll
        for (int off = 1; off < 32; off <<= 1) {
            int t = __shfl_up_sync(0xffffffffu, scan, off);
            if (lane >= off) scan += t;
        }
        if (lane == 31) sm.tk.wagg[wid] = scan;
        __syncthreads();
        if (wid == 0) {
            int v = sm.tk.wagg[lane];
            #pragma unroll
            for (int off = 1; off < 32; off <<= 1) {
                int t = __shfl_up_sync(0xffffffffu, v, off);
                if (lane >= off) v += t;
            }
            sm.tk.wagg[lane] = v;
        }
        __syncthreads();
        int excl = (wid > 0 ? sm.tk.wagg[wid - 1] : 0) + scan - ct;

        for (int j = 0; j < items; ++j) {
            int i = tid * items + j;
            unsigned u = sm.tk.su[i];
            int mk;
            if (u > T) mk = 1;
            else if (u == T) { mk = (excl < r) ? 1 : 0; excl++; }
            else mk = 0;
            mask[i] = mk;
        }
    } else {
        sm.in.cnt[tid] = 0;
        __syncthreads();
        #pragma unroll
        for (int j = 0; j < 4; ++j) {
            int e = j * 1024 + tid;
            int a = g_src[e], b = g_dst[e];
            atomicAdd(&sm.in.cnt[a], 1);
            if (b != a) atomicAdd(&sm.in.cnt[b], 1);
        }
        __syncthreads();
        int own = sm.in.cnt[tid];
        int val = own;
        for (int dd = 1; dd < 1024; dd <<= 1) {
            int t = (tid >= dd) ? sm.in.cnt[tid - dd] : 0;
            __syncthreads();
            val += t;
            sm.in.cnt[tid] = val;
            __syncthreads();
        }
        int offv = val - own;
        sm.in.off[tid] = offv;
        sm.in.pos[tid] = offv;
        if (tid == 1023) g_off[1024] = val;
        g_off[tid] = offv;
        __syncthreads();
        int total = sm.in.cnt[1023];
        #pragma unroll
        for (int j = 0; j < 4; ++j) {
            int e = j * 1024 + tid;
            int a = g_src[e], b = g_dst[e];
            sm.in.inc[atomicAdd(&sm.in.pos[a], 1)] = e;
            if (b != a) sm.in.inc[atomicAdd(&sm.in.pos[b], 1)] = e;
        }
        __syncthreads();
        {
            int s = sm.in.off[tid];
            int t = sm.in.pos[tid];
            for (int i = s + 1; i < t; ++i) {
                int v = sm.in.inc[i];
                int j = i - 1;
                while (j >= s && sm.in.inc[j] > v) { sm.in.inc[j + 1] = sm.in.inc[j]; --j; }
                sm.in.inc[j + 1] = v;
            }
        }
        __syncthreads();
        for (int i = tid; i < total; i += 1024) g_inc[i] = sm.in.inc[i];
    }
}

// ================= GEMM primitives =================
__device__ __forceinline__ void mma_bf16(float* c, const uint32_t* a, const uint32_t* b) {
    asm volatile(
        "mma.sync.aligned.m16n8k16.row.col.f32.bf16.bf16.f32 "
        "{%0,%1,%2,%3}, {%4,%5,%6,%7}, {%8,%9}, {%0,%1,%2,%3};"
        : "+f"(c[0]), "+f"(c[1]), "+f"(c[2]), "+f"(c[3])
        : "r"(a[0]), "r"(a[1]), "r"(a[2]), "r"(a[3]), "r"(b[0]), "r"(b[1]));
}

__device__ __forceinline__ void ldm_x4(uint32_t* r, uint32_t addr) {
    asm volatile("ldmatrix.sync.aligned.m8n8.x4.shared.b16 {%0,%1,%2,%3}, [%4];"
                 : "=r"(r[0]), "=r"(r[1]), "=r"(r[2]), "=r"(r[3]) : "r"(addr));
}

__device__ __forceinline__ void split_store_a(__nv_bfloat16* as_hi, __nv_bfloat16* as_lo,
                                              int o, float4 a) {
    __nv_bfloat16 h0 = __float2bfloat16(a.x), h1 = __float2bfloat16(a.y);
    __nv_bfloat16 h2 = __float2bfloat16(a.z), h3 = __float2bfloat16(a.w);
    __nv_bfloat16 l0 = __float2bfloat16(a.x - __bfloat162float(h0));
    __nv_bfloat16 l1 = __float2bfloat16(a.y - __bfloat162float(h1));
    __nv_bfloat16 l2 = __float2bfloat16(a.z - __bfloat162float(h2));
    __nv_bfloat16 l3 = __float2bfloat16(a.w - __bfloat162float(h3));
    *(__nv_bfloat162*)&as_hi[o]     = __nv_bfloat162(h0, h1);
    *(__nv_bfloat162*)&as_hi[o + 2] = __nv_bfloat162(h2, h3);
    *(__nv_bfloat162*)&as_lo[o]     = __nv_bfloat162(l0, l1);
    *(__nv_bfloat162*)&as_lo[o + 2] = __nv_bfloat162(l2, l3);
}

// copy A chunk [128 x 128] from split-bf16 activation arrays (pure uint4 copy)
__device__ __forceinline__ void copy_a_chunk(__nv_bfloat16* as_hi, __nv_bfloat16* as_lo,
                                             const __nv_bfloat16* Ahi, const __nv_bfloat16* Alo,
                                             int m0, int kc0, int tid) {
    #pragma unroll
    for (int it = 0; it < 8; ++it) {
        int idx = it * 256 + tid;            // 2048 uint4
        int m = idx >> 4, kq = (idx & 15) * 8;
        uint4 vh = *(const uint4*)&Ahi[(size_t)(m0 + m) * D + kc0 + kq];
        uint4 vl = *(const uint4*)&Alo[(size_t)(m0 + m) * D + kc0 + kq];
        *(uint4*)&as_hi[m * APITCH + kq] = vh;
        *(uint4*)&as_lo[m * APITCH + kq] = vl;
    }
}

// fill B chunk [64 x 128] from precomputed transposed weights
__device__ __forceinline__ void fill_b_chunk(__nv_bfloat16* bs_hi, __nv_bfloat16* bs_lo,
                                             int wslot, int n0, int kc0, int tid) {
    const __nv_bfloat16* Bh = g_wthi + (size_t)wslot * D * D;
    const __nv_bfloat16* Bl = g_wtlo + (size_t)wslot * D * D;
    #pragma unroll
    for (int it = 0; it < 4; ++it) {
        int idx = it * 256 + tid;
        int n = idx >> 4, kq = (idx & 15) * 8;
        uint4 vh = *(const uint4*)&Bh[(size_t)(n0 + n) * D + kc0 + kq];
        uint4 vl = *(const uint4*)&Bl[(size_t)(n0 + n) * D + kc0 + kq];
        *(uint4*)&bs_hi[n * BPITCH + kq] = vh;
        *(uint4*)&bs_lo[n * BPITCH + kq] = vl;
    }
}

// 8 k-steps via ldmatrix fragment loads (8 ldmatrix.x4 : 24 HMMA per step)
__device__ __forceinline__ void mma_chunk(uint32_t ah_u, uint32_t al_u,
                                          uint32_t bh_u, uint32_t bl_u,
                                          int wm, int wn, int lane, float acc[2][4][4]) {
    int a_row = wm * 32 + (lane & 15);
    int a_ko = (lane >> 4) << 3;
    uint32_t aoff0 = (uint32_t)((a_row * APITCH + a_ko) * 2);
    uint32_t aoff1 = (uint32_t)(((a_row + 16) * APITCH + a_ko) * 2);
    int b_row = wn * 32 + (lane & 7) + ((lane >> 4) << 3);
    int b_ko = ((lane >> 3) & 1) << 3;
    uint32_t boff0 = (uint32_t)((b_row * BPITCH + b_ko) * 2);
    uint32_t boff1 = (uint32_t)(((b_row + 16) * BPITCH + b_ko) * 2);
    #pragma unroll
    for (int ks = 0; ks < 8; ++ks) {
        uint32_t kb2 = (uint32_t)(ks * 32);  // 16 elems * 2B
        uint32_t ah[2][4], al[2][4], bh[2][4], bl[2][4];
        ldm_x4(ah[0], ah_u + aoff0 + kb2);
        ldm_x4(ah[1], ah_u + aoff1 + kb2);
        ldm_x4(al[0], al_u + aoff0 + kb2);
        ldm_x4(al[1], al_u + aoff1 + kb2);
        ldm_x4(bh[0], bh_u + boff0 + kb2);
        ldm_x4(bh[1], bh_u + boff1 + kb2);
        ldm_x4(bl[0], bl_u + boff0 + kb2);
        ldm_x4(bl[1], bl_u + boff1 + kb2);
        #pragma unroll
        for (int mf = 0; mf < 2; ++mf)
            #pragma unroll
            for (int nf = 0; nf < 4; ++nf) {
                const uint32_t* bhp = &bh[nf >> 1][(nf & 1) * 2];
                const uint32_t* blp = &bl[nf >> 1][(nf & 1) * 2];
                mma_bf16(acc[mf][nf], ah[mf], bhp);
                mma_bf16(acc[mf][nf], ah[mf], blp);
                mma_bf16(acc[mf][nf], al[mf], bhp);
            }
    }
}

// ================= GEMM kernels =================
// generic: A = split pair AID, C = split pair CID, weight wslot, optional gelu
template <int ACT, int AID, int CID>
__global__ void __launch_bounds__(256, 2) k_gemm_sp(int wslot, const float* __restrict__ bias) {
    extern __shared__ __nv_bfloat16 smx[];
    __nv_bfloat16* as_hi = smx + OFF_AHI;
    __nv_bfloat16* as_lo = smx + OFF_ALO;
    __nv_bfloat16* bs_hi = smx + OFF_BHI;
    __nv_bfloat16* bs_lo = smx + OFF_BLO;
    uint32_t ah_u = (uint32_t)__cvta_generic_to_shared(as_hi);
    uint32_t al_u = (uint32_t)__cvta_generic_to_shared(as_lo);
    uint32_t bh_u = (uint32_t)__cvta_generic_to_shared(bs_hi);
    uint32_t bl_u = (uint32_t)__cvta_generic_to_shared(bs_lo);

    int tid = threadIdx.x;
    int wid = tid >> 5, lane = tid & 31;
    int g = lane >> 2, t = lane & 3;
    int wm = wid >> 1, wn = wid & 1;
    int m0 = blockIdx.y * 128, n0 = blockIdx.x * 64;

    float acc[2][4][4] = {};
    #pragma unroll
    for (int kc = 0; kc < 2; ++kc) {
        int kc0 = kc * KC;
        copy_a_chunk(as_hi, as_lo, bufhi<AID>(), buflo<AID>(), m0, kc0, tid);
        fill_b_chunk(bs_hi, bs_lo, wslot, n0, kc0, tid);
        __syncthreads();
        mma_chunk(ah_u, al_u, bh_u, bl_u, wm, wn, lane, acc);
        __syncthreads();
    }

    __nv_bfloat16* Chi = bufhi<CID>();
    __nv_bfloat16* Clo = buflo<CID>();
    #pragma unroll
    for (int mf = 0; mf < 2; ++mf) {
        int r0 = m0 + wm * 32 + mf * 16 + g;
        #pragma unroll
        for (int nf = 0; nf < 4; ++nf) {
            int c = n0 + wn * 32 + nf * 8 + 2 * t;
            float bb0 = bias[c], bb1 = bias[c + 1];
            #pragma unroll
            for (int half = 0; half < 2; ++half) {
                int r = r0 + half * 8;
                float v0 = acc[mf][nf][half * 2 + 0] + bb0;
                float v1 = acc[mf][nf][half * 2 + 1] + bb1;
                if (ACT == 1) {
                    float x0 = v0, x1 = v1;
                    float t0 = tanhf(0.7978845608028654f * (x0 + 0.044715f * x0 * x0 * x0));
                    float t1 = tanhf(0.7978845608028654f * (x1 + 0.044715f * x1 * x1 * x1));
                    v0 = 0.5f * x0 * (1.0f + t0);
                    v1 = 0.5f * x1 * (1.0f + t1);
                }
                __nv_bfloat16 h0 = __float2bfloat16(v0), h1 = __float2bfloat16(v1);
                __nv_bfloat16 l0 = __float2bfloat16(v0 - __bfloat162float(h0));
                __nv_bfloat16 l1 = __float2bfloat16(v1 - __bfloat162float(h1));
                *(__nv_bfloat162*)&Chi[(size_t)r * D + c] = __nv_bfloat162(h0, h1);
                *(__nv_bfloat162*)&Clo[(size_t)r * D + c] = __nv_bfloat162(l0, l1);
            }
        }
    }
}

// h GEMM: A generated on the fly (nf[src]+nf[dst]); epilogue adds masked ef; writes split h
__global__ void __launch_bounds__(256, 2) k_gemm_h(const float* __restrict__ nf,
                                                   const float* __restrict__ efi,
                                                   const float* __restrict__ bias) {
    extern __shared__ __nv_bfloat16 smx[];
    __nv_bfloat16* as_hi = smx + OFF_AHI;
    __nv_bfloat16* as_lo = smx + OFF_ALO;
    __nv_bfloat16* bs_hi = smx + OFF_BHI;
    __nv_bfloat16* bs_lo = smx + OFF_BLO;
    uint32_t ah_u = (uint32_t)__cvta_generic_to_shared(as_hi);
    uint32_t al_u = (uint32_t)__cvta_generic_to_shared(as_lo);
    uint32_t bh_u = (uint32_t)__cvta_generic_to_shared(bs_hi);
    uint32_t bl_u = (uint32_t)__cvta_generic_to_shared(bs_lo);

    int tid = threadIdx.x;
    int wid = tid >> 5, lane = tid & 31;
    int g = lane >> 2, t = lane & 3;
    int wm = wid >> 1, wn = wid & 1;
    int m0 = blockIdx.y * 128, n0 = blockIdx.x * 64;

    float acc[2][4][4] = {};
    #pragma unroll
    for (int kc = 0; kc < 2; ++kc) {
        int kc0 = kc * KC;
        #pragma unroll
        for (int it = 0; it < 16; ++it) {
            int idx = it * 256 + tid;
            int m = idx >> 5, k4 = (idx & 31) * 4;
            int e = m0 + m;
            int a = g_src[e], b = g_dst[e];
            float4 xa = *(const float4*)&nf[(size_t)a * D + kc0 + k4];
            float4 xb = *(const float4*)&nf[(size_t)b * D + kc0 + k4];
            float4 s = {xa.x + xb.x, xa.y + xb.y, xa.z + xb.z, xa.w + xb.w};
            split_store_a(as_hi, as_lo, m * APITCH + k4, s);
        }
        fill_b_chunk(bs_hi, bs_lo, 0, n0, kc0, tid);
        __syncthreads();
        mma_chunk(ah_u, al_u, bh_u, bl_u, wm, wn, lane, acc);
        __syncthreads();
    }

    #pragma unroll
    for (int mf = 0; mf < 2; ++mf) {
        int r0 = m0 + wm * 32 + mf * 16 + g;
        #pragma unroll
        for (int half = 0; half < 2; ++half) {
            int r = r0 + half * 8;
            int em = g_emask[r] & g_nmask[g_src[r]] & g_nmask[g_dst[r]];
            float fm = em ? 1.0f : 0.0f;
            #pragma unroll
            for (int nf = 0; nf < 4; ++nf) {
                int c = n0 + wn * 32 + nf * 8 + 2 * t;
                float v0 = acc[mf][nf][half * 2 + 0] + bias[c]
                         + fm * efi[(size_t)r * D + c];
                float v1 = acc[mf][nf][half * 2 + 1] + bias[c + 1]
                         + fm * efi[(size_t)r * D + c + 1];
                __nv_bfloat16 h0 = __float2bfloat16(v0), h1 = __float2bfloat16(v1);
                __nv_bfloat16 l0 = __float2bfloat16(v0 - __bfloat162float(h0));
                __nv_bfloat16 l1 = __float2bfloat16(v1 - __bfloat162float(h1));
                *(__nv_bfloat162*)&g_hhi[(size_t)r * D + c] = __nv_bfloat162(h0, h1);
                *(__nv_bfloat162*)&g_hlo[(size_t)r * D + c] = __nv_bfloat162(l0, l1);
            }
        }
    }
}

// qkv GEMM: A = split h, C = fp32 q/k/v (consumed by scalar attention)
__global__ void __launch_bounds__(256, 2) k_gemm_qkv(
        const float* __restrict__ bq, const float* __restrict__ bk,
        const float* __restrict__ bv) {
    extern __shared__ __nv_bfloat16 smx[];
    __nv_bfloat16* as_hi = smx + OFF_AHI;
    __nv_bfloat16* as_lo = smx + OFF_ALO;
    __nv_bfloat16* bs_hi = smx + OFF_BHI;
    __nv_bfloat16* bs_lo = smx + OFF_BLO;
    uint32_t ah_u = (uint32_t)__cvta_generic_to_shared(as_hi);
    uint32_t al_u = (uint32_t)__cvta_generic_to_shared(as_lo);
    uint32_t bh_u = (uint32_t)__cvta_generic_to_shared(bs_hi);
    uint32_t bl_u = (uint32_t)__cvta_generic_to_shared(bs_lo);

    const float* bias;
    float* C;
    if (blockIdx.z == 0)      { bias = bq; C = g_q; }
    else if (blockIdx.z == 1) { bias = bk; C = g_k; }
    else                      { bias = bv; C = g_v; }
    int wslot = 1 + blockIdx.z;

    int tid = threadIdx.x;
    int wid = tid >> 5, lane = tid & 31;
    int g = lane >> 2, t = lane & 3;
    int wm = wid >> 1, wn = wid & 1;
    int m0 = blockIdx.y * 128, n0 = blockIdx.x * 64;

    float acc[2][4][4] = {};
    #pragma unroll
    for (int kc = 0; kc < 2; ++kc) {
        int kc0 = kc * KC;
        copy_a_chunk(as_hi, as_lo, g_hhi, g_hlo, m0, kc0, tid);
        fill_b_chunk(bs_hi, bs_lo, wslot, n0, kc0, tid);
        __syncthreads();
        mma_chunk(ah_u, al_u, bh_u, bl_u, wm, wn, lane, acc);
        __syncthreads();
    }

    #pragma unroll
    for (int mf = 0; mf < 2; ++mf) {
        int r0 = m0 + wm * 32 + mf * 16 + g;
        #pragma unroll
        for (int nf = 0; nf < 4; ++nf) {
            int c = n0 + wn * 32 + nf * 8 + 2 * t;
            float bb0 = bias[c], bb1 = bias[c + 1];
            #pragma unroll
            for (int half = 0; half < 2; ++half) {
                int r = r0 + half * 8;
                float2 o2 = {acc[mf][nf][half * 2 + 0] + bb0,
                             acc[mf][nf][half * 2 + 1] + bb1};
                *(float2*)&C[(size_t)r * D + c] = o2;
            }
        }
    }
}

// ================= sparse masked attention =================
__global__ void k_attn() {
    __shared__ int s_cand[MAXC];
    __shared__ float s_sc[HN][MAXC];
    __shared__ int s_n;
    int e = blockIdx.x;
    int tid = threadIdx.x;
    int h = tid >> 5, lane = tid & 31;
    int a = g_src[e], b = g_dst[e];
    int oa = g_off[a];
    int na = g_off[a + 1] - oa;

    for (int i = tid; i < na; i += 128) s_cand[i] = g_inc[oa + i];

    if (tid < 32) {
        int cnt = na;
        if (b != a) {
            int ob = g_off[b];
            int nb = g_off[b + 1] - ob;
            for (int i0 = 0; i0 < nb; i0 += 32) {
                int i = i0 + lane;
                int f = 0, keep = 0;
                if (i < nb) {
                    f = g_inc[ob + i];
                    keep = (g_src[f] != a && g_dst[f] != a) ? 1 : 0;
                }
                unsigned bal = __ballot_sync(0xffffffffu, keep != 0);
                if (keep) {
                    int pos = cnt + __popc(bal & ((1u << lane) - 1u));
                    if (pos < MAXC) s_cand[pos] = f;
                }
                cnt += __popc(bal);
            }
        }
        if (lane == 0) s_n = (cnt < MAXC) ? cnt : MAXC;
    }
    __syncthreads();
    int nc = s_n;
    int base = e * D + h * DHD;

    float2 q2 = *(const float2*)&g_q[base + lane * 2];

    for (int c = 0; c < nc; ++c) {
        int f = s_cand[c];
        float2 k2 = *(const float2*)&g_k[f * D + h * DHD + lane * 2];
        float s = q2.x * k2.x + q2.y * k2.y;
        #pragma unroll
        for (int o = 16; o; o >>= 1) s += __shfl_xor_sync(0xffffffffu, s, o);
        if (lane == 0) s_sc[h][c] = s * 0.125f;
    }
    __syncwarp();

    float mx = -3.0e38f;
    for (int c = lane; c < nc; c += 32) mx = fmaxf(mx, s_sc[h][c]);
    #pragma unroll
    for (int o = 16; o; o >>= 1) mx = fmaxf(mx, __shfl_xor_sync(0xffffffffu, mx, o));
    float l = 0.f;
    for (int c = lane; c < nc; c += 32) {
        float p = __expf(s_sc[h][c] - mx);
        s_sc[h][c] = p;
        l += p;
    }
    #pragma unroll
    for (int o = 16; o; o >>= 1) l += __shfl_xor_sync(0xffffffffu, l, o);
    __syncwarp();

    float ax = 0.f, ay = 0.f;
    for (int c = 0; c < nc; ++c) {
        float p = s_sc[h][c];
        float2 v2 = *(const float2*)&g_v[s_cand[c] * D + h * DHD + lane * 2];
        ax += p * v2.x;
        ay += p * v2.y;
    }
    float inv = 1.f / l;
    float vx = ax * inv, vy = ay * inv;
    __nv_bfloat16 hx = __float2bfloat16(vx), hy = __float2bfloat16(vy);
    __nv_bfloat16 lx = __float2bfloat16(vx - __bfloat162float(hx));
    __nv_bfloat16 ly = __float2bfloat16(vy - __bfloat162float(hy));
    *(__nv_bfloat162*)&g_aohi[base + lane * 2] = __nv_bfloat162(hx, hy);
    *(__nv_bfloat162*)&g_aolo[base + lane * 2] = __nv_bfloat162(lx, ly);
}

// ================= classifier =================
__global__ void k_cls(const float* __restrict__ W2, const float* __restrict__ b2,
                      float* __restrict__ out) {
    int warp = (blockIdx.x * blockDim.x + threadIdx.x) >> 5;
    int lane = threadIdx.x & 31;
    if (warp >= NE) return;
    float x[8];
    #pragma unroll
    for (int i = 0; i < 8; ++i) {
        size_t id = (size_t)warp * D + lane + i * 32;
        x[i] = __bfloat162float(g_hidhi[id]) + __bfloat162float(g_hidlo[id]);
    }
    float res = 0.f;
    #pragma unroll
    for (int c = 0; c < CLS; ++c) {
        float s = 0.f;
        #pragma unroll
        for (int i = 0; i < 8; ++i) s += x[i] * W2[(size_t)(lane + i * 32) * CLS + c];
        #pragma unroll
        for (int o = 16; o; o >>= 1) s += __shfl_xor_sync(0xffffffffu, s, o);
        if (lane == c) res = s + b2[c];
    }
    if (lane < CLS) out[(size_t)warp * CLS + lane] = res;
}

// ================= host =================
extern "C" void kernel_launch(void* const* d_in, const int* in_sizes, int n_in,
                              void* d_out, int out_size) {
    const float* nf   = (const float*)d_in[0];
    const float* efi  = (const float*)d_in[1];
    const int*   ei   = (const int*)d_in[2];
    const float* Wn_r = (const float*)d_in[3];
    const float* bn_r = (const float*)d_in[4];
    const float* We_r = (const float*)d_in[5];
    const float* be_r = (const float*)d_in[6];
    const float* Wnp  = (const float*)d_in[7];
    const float* bnp  = (const float*)d_in[8];
    const float* Wq   = (const float*)d_in[9];
    const float* bq   = (const float*)d_in[10];
    const float* Wk   = (const float*)d_in[11];
    const float* bk   = (const float*)d_in[12];
    const float* Wv   = (const float*)d_in[13];
    const float* bv   = (const float*)d_in[14];
    const float* Wo   = (const float*)d_in[15];
    const float* bo   = (const float*)d_in[16];
    const float* W1   = (const float*)d_in[17];
    const float* b1   = (const float*)d_in[18];
    const float* W2   = (const float*)d_in[19];
    const float* b2   = (const float*)d_in[20];
    float* out = (float*)d_out;

    cudaFuncSetAttribute(k_gemm_h, cudaFuncAttributeMaxDynamicSharedMemorySize, MMA_SMEM_BYTES);
    cudaFuncSetAttribute(k_gemm_qkv, cudaFuncAttributeMaxDynamicSharedMemorySize, MMA_SMEM_BYTES);
    cudaFuncSetAttribute(k_gemm_sp<0, 1, 2>, cudaFuncAttributeMaxDynamicSharedMemorySize, MMA_SMEM_BYTES);
    cudaFuncSetAttribute(k_gemm_sp<1, 2, 3>, cudaFuncAttributeMaxDynamicSharedMemorySize, MMA_SMEM_BYTES);

    k_front<<<752, 256>>>(nf, efi, ei, Wn_r, bn_r, We_r, be_r, Wnp, Wq, Wk, Wv, Wo, W1);
    k_build<<<3, 1024>>>();

    dim3 gg(D / 64, NE / 128);      // (4, 32)
    dim3 gq(D / 64, NE / 128, 3);   // fused q/k/v
    k_gemm_h<<<gg, 256, MMA_SMEM_BYTES>>>(nf, efi, bnp);       // h (split) = (nf[s]+nf[d])@Wnp + bnp + mask*ef
    k_gemm_qkv<<<gq, 256, MMA_SMEM_BYTES>>>(bq, bk, bv);       // q,k,v fp32
    k_attn<<<NE, 128>>>();                                     // ao (split)
    k_gemm_sp<0, 1, 2><<<gg, 256, MMA_SMEM_BYTES>>>(4, bo);    // o (split) = ao@Wo + bo
    k_gemm_sp<1, 2, 3><<<gg, 256, MMA_SMEM_BYTES>>>(5, b1);    // hid (split) = gelu(o@W1 + b1)
    k_cls<<<(NE * 32 + 255) / 256, 256>>>(W2, b2, out);
}

// round 11
// speedup vs baseline: 1.0502x; 1.0502x over previous
#include <cuda_runtime.h>
#include <cuda_bf16.h>
#include <math.h>
#include <stdint.h>

#define NN    1024
#define NE    4096
#define D     256
#define HN    4
#define DHD   64
#define NODEK 512
#define EDGEK 2048
#define CLS   16
#define MAXC  1024

// full-K resident GEMM: CTA 128x64, K=256, 8 warps (4m x 2n), warp 32x32
#define FAPITCH 264
#define F_AHI 0
#define F_ALO (128 * FAPITCH)
#define F_BHI (2 * 128 * FAPITCH)
#define F_BLO (2 * 128 * FAPITCH + 64 * FAPITCH)
#define F_ELEMS (2 * 128 * FAPITCH + 2 * 64 * FAPITCH)
#define F_BYTES (F_ELEMS * 2)   // 202752 B -> 1 CTA/SM (grid <= 148 anyway)

// ---------------- scratch ----------------
__device__ float g_nscore[NN];
__device__ float g_escore[NE];
__device__ int   g_nmask[NN];
__device__ int   g_emask[NE];
__device__ int   g_src[NE], g_dst[NE];
__device__ int   g_off[NN + 1];
__device__ int   g_inc[2 * NE];
__device__ float g_q[NE * D];
__device__ float g_k[NE * D];
__device__ float g_v[NE * D];
// split-bf16 activations (hi + residual lo)
__device__ __nv_bfloat16 g_hhi[NE * D],   g_hlo[NE * D];    // pair 0
__device__ __nv_bfloat16 g_aohi[NE * D],  g_aolo[NE * D];   // pair 1
__device__ __nv_bfloat16 g_ohi[NE * D],   g_olo[NE * D];    // pair 2
__device__ __nv_bfloat16 g_hidhi[NE * D], g_hidlo[NE * D];  // pair 3
// transposed split-bf16 weights: [w][n][k], w: 0=Wnp 1=Wq 2=Wk 3=Wv 4=Wo 5=W1
__device__ __nv_bfloat16 g_wthi[6 * D * D];
__device__ __nv_bfloat16 g_wtlo[6 * D * D];

template <int ID> __device__ __forceinline__ __nv_bfloat16* bufhi();
template <> __device__ __forceinline__ __nv_bfloat16* bufhi<0>() { return g_hhi; }
template <> __device__ __forceinline__ __nv_bfloat16* bufhi<1>() { return g_aohi; }
template <> __device__ __forceinline__ __nv_bfloat16* bufhi<2>() { return g_ohi; }
template <> __device__ __forceinline__ __nv_bfloat16* bufhi<3>() { return g_hidhi; }
template <int ID> __device__ __forceinline__ __nv_bfloat16* buflo();
template <> __device__ __forceinline__ __nv_bfloat16* buflo<0>() { return g_hlo; }
template <> __device__ __forceinline__ __nv_bfloat16* buflo<1>() { return g_aolo; }
template <> __device__ __forceinline__ __nv_bfloat16* buflo<2>() { return g_olo; }
template <> __device__ __forceinline__ __nv_bfloat16* buflo<3>() { return g_hidlo; }

// ================= 1: fused front-end =================
__global__ void k_front(const float* __restrict__ nf, const float* __restrict__ efi,
                        const int* __restrict__ ei,
                        const float* __restrict__ Wn, const float* __restrict__ bn,
                        const float* __restrict__ We, const float* __restrict__ be,
                        const float* __restrict__ Wnp, const float* __restrict__ Wq,
                        const float* __restrict__ Wk, const float* __restrict__ Wv,
                        const float* __restrict__ Wo, const float* __restrict__ W1) {
    int b = blockIdx.x;
    int tid = threadIdx.x;
    if (b < 96) {
        __shared__ float s[64][65];
        int w = b >> 4, t16 = b & 15;
        const float* W;
        switch (w) {
            case 0: W = Wnp; break;
            case 1: W = Wq; break;
            case 2: W = Wk; break;
            case 3: W = Wv; break;
            case 4: W = Wo; break;
            default: W = W1; break;
        }
        int n0 = (t16 & 3) * 64, k0 = (t16 >> 2) * 64;
        int n4 = (tid & 15) * 4, kr = tid >> 4;
        #pragma unroll
        for (int kk = kr; kk < 64; kk += 16) {
            float4 v = *(const float4*)&W[(size_t)(k0 + kk) * D + n0 + n4];
            s[kk][n4] = v.x;
            s[kk][n4 + 1] = v.y;
            s[kk][n4 + 2] = v.z;
            s[kk][n4 + 3] = v.w;
        }
        __syncthreads();
        int nl = tid >> 2, kq = (tid & 3) * 16;
        __nv_bfloat16 hi[16], lo[16];
        #pragma unroll
        for (int i = 0; i < 16; ++i) {
            float x = s[kq + i][nl];
            hi[i] = __float2bfloat16(x);
            lo[i] = __float2bfloat16(x - __bfloat162float(hi[i]));
        }
        size_t off = (size_t)w * D * D + (size_t)(n0 + nl) * D + k0 + kq;
        *(uint4*)&g_wthi[off] = *(uint4*)&hi[0];
        *(uint4*)&g_wthi[off + 8] = *(uint4*)&hi[8];
        *(uint4*)&g_wtlo[off] = *(uint4*)&lo[0];
        *(uint4*)&g_wtlo[off + 8] = *(uint4*)&lo[8];
    } else if (b < 112) {
        __shared__ int sh[256];
        int acc = 0;
        for (int i = tid; i < 2048; i += 256) acc |= ei[2 * i + 1];
        sh[tid] = acc;
        __syncthreads();
        for (int s2 = 128; s2 > 0; s2 >>= 1) {
            if (tid < s2) sh[tid] |= sh[tid + s2];
            __syncthreads();
        }
        int is64 = (sh[0] == 0) ? 1 : 0;
        int i = (b - 96) * 256 + tid;
        int s, d;
        if (is64) { s = ei[2 * i]; d = ei[2 * (NE + i)]; }
        else      { s = ei[i];     d = ei[NE + i]; }
        g_src[i] = s;
        g_dst[i] = d;
    } else {
        int warp = (b - 112) * 8 + (tid >> 5);
        int lane = tid & 31;
        const float* x;
        const float* w;
        if (warp < NN) { x = nf + (size_t)warp * D; w = Wn; }
        else           { x = efi + (size_t)(warp - NN) * D; w = We; }
        float s = 0.f;
        #pragma unroll
        for (int i = 0; i < D / 32; ++i) s += x[lane + i * 32] * w[lane + i * 32];
        #pragma unroll
        for (int o = 16; o; o >>= 1) s += __shfl_xor_sync(0xffffffffu, s, o);
        if (lane == 0) {
            if (warp < NN) g_nscore[warp] = s + bn[0];
            else           g_escore[warp - NN] = s + be[0];
        }
    }
}

// ================= 2: fused build =================
struct TkSmem {
    unsigned su[NE];
    int hist[256];
    unsigned pref;
    int krem;
    int wagg[32];
};
struct IncSmem {
    int cnt[NN];
    int off[NN];
    int pos[NN];
    int inc[2 * NE];
};
union BuildSmem {
    TkSmem tk;
    IncSmem in;
};

__global__ void __launch_bounds__(1024, 1) k_build() {
    __shared__ BuildSmem sm;
    int tid = threadIdx.x;
    int lane = tid & 31, wid = tid >> 5;

    if (blockIdx.x < 2) {
        const bool is_edge = (blockIdx.x == 1);
        const float* sc = is_edge ? g_escore : g_nscore;
        int* mask = is_edge ? g_emask : g_nmask;
        const int n = is_edge ? NE : NN;
        const int kk = is_edge ? EDGEK : NODEK;
        int items = n >> 10;

        for (int j = 0; j < items; ++j) {
            int i = tid * items + j;
            unsigned bb = __float_as_uint(sc[i]);
            sm.tk.su[i] = (bb & 0x80000000u) ? ~bb : (bb | 0x80000000u);
        }
        if (tid == 0) { sm.tk.pref = 0u; sm.tk.krem = kk; }
        __syncthreads();

        for (int shift = 24; shift >= 0; shift -= 8) {
            unsigned prefix = sm.tk.pref;
            unsigned done_mask = (shift == 24) ? 0u : (0xFFFFFFFFu << (shift + 8));
            if (tid < 256) sm.tk.hist[tid] = 0;
            __syncthreads();
            for (int j = 0; j < items; ++j) {
                unsigned u = sm.tk.su[tid * items + j];
                if ((u & done_mask) == prefix)
                    atomicAdd(&sm.tk.hist[(u >> shift) & 255], 1);
            }
            __syncthreads();
            if (wid == 0) {
                int krem = sm.tk.krem;
                int gsum = 0;
                #pragma unroll
                for (int c = 0; c < 8; ++c) gsum += sm.tk.hist[lane * 8 + c];
                int x = gsum;
                #pragma unroll
                for (int off = 1; off < 32; off <<= 1) {
                    int t = __shfl_down_sync(0xffffffffu, x, off);
                    if (lane + off < 32) x += t;
                }
                int above = x - gsum;
                bool hit = (above < krem) && (x >= krem);
                unsigned bal = __ballot_sync(0xffffffffu, hit);
                int srcl = __ffs(bal) - 1;
                if (lane == srcl) {
                    int cum = above;
                    #pragma unroll
                    for (int c = 7; c >= 0; --c) {
                        int bb = lane * 8 + c;
                        int hc = sm.tk.hist[bb];
                        if (cum + hc >= krem) {
                            sm.tk.pref = prefix | ((unsigned)bb << shift);
                            sm.tk.krem = krem - cum;
                            break;
                        }
                        cum += hc;
                    }
                }
            }
            __syncthreads();
        }
        unsigned T = sm.tk.pref;
        int r = sm.tk.krem;

        int ct = 0;
        for (int j = 0; j < items; ++j) ct += (sm.tk.su[tid * items + j] == T) ? 1 : 0;
        int scan = ct;
        #pragma unroll
        for (int off = 1; off < 32; off <<= 1) {
            int t = __shfl_up_sync(0xffffffffu, scan, off);
            if (lane >= off) scan += t;
        }
        if (lane == 31) sm.tk.wagg[wid] = scan;
        __syncthreads();
        if (wid == 0) {
            int v = sm.tk.wagg[lane];
            #pragma unroll
            for (int off = 1; off < 32; off <<= 1) {
                int t = __shfl_up_sync(0xffffffffu, v, off);
                if (lane >= off) v += t;
            }
            sm.tk.wagg[lane] = v;
        }
        __syncthreads();
        int excl = (wid > 0 ? sm.tk.wagg[wid - 1] : 0) + scan - ct;

        for (int j = 0; j < items; ++j) {
            int i = tid * items + j;
            unsigned u = sm.tk.su[i];
            int mk;
            if (u > T) mk = 1;
            else if (u == T) { mk = (excl < r) ? 1 : 0; excl++; }
            else mk = 0;
            mask[i] = mk;
        }
    } else {
        sm.in.cnt[tid] = 0;
        __syncthreads();
        #pragma unroll
        for (int j = 0; j < 4; ++j) {
            int e = j * 1024 + tid;
            int a = g_src[e], b = g_dst[e];
            atomicAdd(&sm.in.cnt[a], 1);
            if (b != a) atomicAdd(&sm.in.cnt[b], 1);
        }
        __syncthreads();
        int own = sm.in.cnt[tid];
        int val = own;
        for (int dd = 1; dd < 1024; dd <<= 1) {
            int t = (tid >= dd) ? sm.in.cnt[tid - dd] : 0;
            __syncthreads();
            val += t;
            sm.in.cnt[tid] = val;
            __syncthreads();
        }
        int offv = val - own;
        sm.in.off[tid] = offv;
        sm.in.pos[tid] = offv;
        if (tid == 1023) g_off[1024] = val;
        g_off[tid] = offv;
        __syncthreads();
        int total = sm.in.cnt[1023];
        #pragma unroll
        for (int j = 0; j < 4; ++j) {
            int e = j * 1024 + tid;
            int a = g_src[e], b = g_dst[e];
            sm.in.inc[atomicAdd(&sm.in.pos[a], 1)] = e;
            if (b != a) sm.in.inc[atomicAdd(&sm.in.pos[b], 1)] = e;
        }
        __syncthreads();
        {
            int s = sm.in.off[tid];
            int t = sm.in.pos[tid];
            for (int i = s + 1; i < t; ++i) {
                int v = sm.in.inc[i];
                int j = i - 1;
                while (j >= s && sm.in.inc[j] > v) { sm.in.inc[j + 1] = sm.in.inc[j]; --j; }
                sm.in.inc[j + 1] = v;
            }
        }
        __syncthreads();
        for (int i = tid; i < total; i += 1024) g_inc[i] = sm.in.inc[i];
    }
}

// ================= GEMM primitives =================
__device__ __forceinline__ void mma_bf16(float* c, const uint32_t* a, const uint32_t* b) {
    asm volatile(
        "mma.sync.aligned.m16n8k16.row.col.f32.bf16.bf16.f32 "
        "{%0,%1,%2,%3}, {%4,%5,%6,%7}, {%8,%9}, {%0,%1,%2,%3};"
        : "+f"(c[0]), "+f"(c[1]), "+f"(c[2]), "+f"(c[3])
        : "r"(a[0]), "r"(a[1]), "r"(a[2]), "r"(a[3]), "r"(b[0]), "r"(b[1]));
}

__device__ __forceinline__ void ldm_x4(uint32_t* r, uint32_t addr) {
    asm volatile("ldmatrix.sync.aligned.m8n8.x4.shared.b16 {%0,%1,%2,%3}, [%4];"
                 : "=r"(r[0]), "=r"(r[1]), "=r"(r[2]), "=r"(r[3]) : "r"(addr));
}

__device__ __forceinline__ void cp16(uint32_t s, const void* g) {
    asm volatile("cp.async.cg.shared.global [%0], [%1], 16;" :: "r"(s), "l"(g));
}
__device__ __forceinline__ void cp_commit() {
    asm volatile("cp.async.commit_group;" ::: "memory");
}
__device__ __forceinline__ void cp_wait0() {
    asm volatile("cp.async.wait_group 0;" ::: "memory");
}

__device__ __forceinline__ void split_store_a(__nv_bfloat16* as_hi, __nv_bfloat16* as_lo,
                                              int o, float4 a) {
    __nv_bfloat16 h0 = __float2bfloat16(a.x), h1 = __float2bfloat16(a.y);
    __nv_bfloat16 h2 = __float2bfloat16(a.z), h3 = __float2bfloat16(a.w);
    __nv_bfloat16 l0 = __float2bfloat16(a.x - __bfloat162float(h0));
    __nv_bfloat16 l1 = __float2bfloat16(a.y - __bfloat162float(h1));
    __nv_bfloat16 l2 = __float2bfloat16(a.z - __bfloat162float(h2));
    __nv_bfloat16 l3 = __float2bfloat16(a.w - __bfloat162float(h3));
    *(__nv_bfloat162*)&as_hi[o]     = __nv_bfloat162(h0, h1);
    *(__nv_bfloat162*)&as_hi[o + 2] = __nv_bfloat162(h2, h3);
    *(__nv_bfloat162*)&as_lo[o]     = __nv_bfloat162(l0, l1);
    *(__nv_bfloat162*)&as_lo[o + 2] = __nv_bfloat162(l2, l3);
}

// async copy A [128 x 256] (hi+lo) into full-K smem
__device__ __forceinline__ void cp_a_full(uint32_t ah_u, uint32_t al_u,
                                          const __nv_bfloat16* Ahi, const __nv_bfloat16* Alo,
                                          int m0, int tid) {
    #pragma unroll
    for (int it = 0; it < 16; ++it) {
        int idx = it * 256 + tid;            // 4096 16B chunks per array
        int m = idx >> 5, kq = (idx & 31) * 8;
        uint32_t so = (uint32_t)((m * FAPITCH + kq) * 2);
        cp16(ah_u + so, &Ahi[(size_t)(m0 + m) * D + kq]);
        cp16(al_u + so, &Alo[(size_t)(m0 + m) * D + kq]);
    }
}

// async copy B [64 x 256] (hi+lo) for weight wslot
__device__ __forceinline__ void cp_b_full(uint32_t bh_u, uint32_t bl_u,
                                          int wslot, int n0, int tid) {
    const __nv_bfloat16* Bh = g_wthi + (size_t)wslot * D * D;
    const __nv_bfloat16* Bl = g_wtlo + (size_t)wslot * D * D;
    #pragma unroll
    for (int it = 0; it < 8; ++it) {
        int idx = it * 256 + tid;            // 2048 16B chunks per array
        int n = idx >> 5, kq = (idx & 31) * 8;
        uint32_t so = (uint32_t)((n * FAPITCH + kq) * 2);
        cp16(bh_u + so, &Bh[(size_t)(n0 + n) * D + kq]);
        cp16(bl_u + so, &Bl[(size_t)(n0 + n) * D + kq]);
    }
}

// full-K mma: 16 k-steps via ldmatrix (8 ldmatrix.x4 : 24 HMMA per step)
__device__ __forceinline__ void mma_full(uint32_t ah_u, uint32_t al_u,
                                         uint32_t bh_u, uint32_t bl_u,
                                         int wm, int wn, int lane, float acc[2][4][4]) {
    int a_row = wm * 32 + (lane & 15);
    int a_ko = (lane >> 4) << 3;
    uint32_t aoff0 = (uint32_t)((a_row * FAPITCH + a_ko) * 2);
    uint32_t aoff1 = (uint32_t)(((a_row + 16) * FAPITCH + a_ko) * 2);
    int b_row = wn * 32 + (lane & 7) + ((lane >> 4) << 3);
    int b_ko = ((lane >> 3) & 1) << 3;
    uint32_t boff0 = (uint32_t)((b_row * FAPITCH + b_ko) * 2);
    uint32_t boff1 = (uint32_t)(((b_row + 16) * FAPITCH + b_ko) * 2);
    #pragma unroll
    for (int ks = 0; ks < 16; ++ks) {
        uint32_t kb2 = (uint32_t)(ks * 32);  // 16 elems * 2B
        uint32_t ah[2][4], al[2][4], bh[2][4], bl[2][4];
        ldm_x4(ah[0], ah_u + aoff0 + kb2);
        ldm_x4(ah[1], ah_u + aoff1 + kb2);
        ldm_x4(al[0], al_u + aoff0 + kb2);
        ldm_x4(al[1], al_u + aoff1 + kb2);
        ldm_x4(bh[0], bh_u + boff0 + kb2);
        ldm_x4(bh[1], bh_u + boff1 + kb2);
        ldm_x4(bl[0], bl_u + boff0 + kb2);
        ldm_x4(bl[1], bl_u + boff1 + kb2);
        #pragma unroll
        for (int mf = 0; mf < 2; ++mf)
            #pragma unroll
            for (int nf = 0; nf < 4; ++nf) {
                const uint32_t* bhp = &bh[nf >> 1][(nf & 1) * 2];
                const uint32_t* blp = &bl[nf >> 1][(nf & 1) * 2];
                mma_bf16(acc[mf][nf], ah[mf], bhp);
                mma_bf16(acc[mf][nf], ah[mf], blp);
                mma_bf16(acc[mf][nf], al[mf], bhp);
            }
    }
}

// ================= GEMM kernels =================
// generic split->split: A pair AID, C pair CID, weight wslot, optional gelu
template <int ACT, int AID, int CID>
__global__ void __launch_bounds__(256) k_gemm_sp(int wslot, const float* __restrict__ bias) {
    extern __shared__ __nv_bfloat16 smx[];
    uint32_t base = (uint32_t)__cvta_generic_to_shared(smx);
    uint32_t ah_u = base + F_AHI * 2, al_u = base + F_ALO * 2;
    uint32_t bh_u = base + F_BHI * 2, bl_u = base + F_BLO * 2;

    int tid = threadIdx.x;
    int wid = tid >> 5, lane = tid & 31;
    int g = lane >> 2, t = lane & 3;
    int wm = wid >> 1, wn = wid & 1;
    int m0 = blockIdx.y * 128, n0 = blockIdx.x * 64;

    cp_b_full(bh_u, bl_u, wslot, n0, tid);
    cp_a_full(ah_u, al_u, bufhi<AID>(), buflo<AID>(), m0, tid);
    cp_commit();
    cp_wait0();
    __syncthreads();

    float acc[2][4][4] = {};
    mma_full(ah_u, al_u, bh_u, bl_u, wm, wn, lane, acc);

    __nv_bfloat16* Chi = bufhi<CID>();
    __nv_bfloat16* Clo = buflo<CID>();
    #pragma unroll
    for (int mf = 0; mf < 2; ++mf) {
        int r0 = m0 + wm * 32 + mf * 16 + g;
        #pragma unroll
        for (int nf = 0; nf < 4; ++nf) {
            int c = n0 + wn * 32 + nf * 8 + 2 * t;
            float bb0 = bias[c], bb1 = bias[c + 1];
            #pragma unroll
            for (int half = 0; half < 2; ++half) {
                int r = r0 + half * 8;
                float v0 = acc[mf][nf][half * 2 + 0] + bb0;
                float v1 = acc[mf][nf][half * 2 + 1] + bb1;
                if (ACT == 1) {
                    float x0 = v0, x1 = v1;
                    float t0 = tanhf(0.7978845608028654f * (x0 + 0.044715f * x0 * x0 * x0));
                    float t1 = tanhf(0.7978845608028654f * (x1 + 0.044715f * x1 * x1 * x1));
                    v0 = 0.5f * x0 * (1.0f + t0);
                    v1 = 0.5f * x1 * (1.0f + t1);
                }
                __nv_bfloat16 h0 = __float2bfloat16(v0), h1 = __float2bfloat16(v1);
                __nv_bfloat16 l0 = __float2bfloat16(v0 - __bfloat162float(h0));
                __nv_bfloat16 l1 = __float2bfloat16(v1 - __bfloat162float(h1));
                *(__nv_bfloat162*)&Chi[(size_t)r * D + c] = __nv_bfloat162(h0, h1);
                *(__nv_bfloat162*)&Clo[(size_t)r * D + c] = __nv_bfloat162(l0, l1);
            }
        }
    }
}

// h GEMM: A computed on the fly (nf[src]+nf[dst]); epilogue adds masked ef; writes split h
__global__ void __launch_bounds__(256) k_gemm_h(const float* __restrict__ nf,
                                                const float* __restrict__ efi,
                                                const float* __restrict__ bias) {
    extern __shared__ __nv_bfloat16 smx[];
    __nv_bfloat16* as_hi = smx + F_AHI;
    __nv_bfloat16* as_lo = smx + F_ALO;
    uint32_t base = (uint32_t)__cvta_generic_to_shared(smx);
    uint32_t ah_u = base + F_AHI * 2, al_u = base + F_ALO * 2;
    uint32_t bh_u = base + F_BHI * 2, bl_u = base + F_BLO * 2;

    int tid = threadIdx.x;
    int wid = tid >> 5, lane = tid & 31;
    int g = lane >> 2, t = lane & 3;
    int wm = wid >> 1, wn = wid & 1;
    int m0 = blockIdx.y * 128, n0 = blockIdx.x * 64;

    cp_b_full(bh_u, bl_u, 0, n0, tid);   // async B while we compute A
    cp_commit();
    #pragma unroll
    for (int it = 0; it < 32; ++it) {
        int idx = it * 256 + tid;        // 8192 float4
        int m = idx >> 6, k4 = (idx & 63) * 4;
        int e = m0 + m;
        int a = g_src[e], b = g_dst[e];
        float4 xa = *(const float4*)&nf[(size_t)a * D + k4];
        float4 xb = *(const float4*)&nf[(size_t)b * D + k4];
        float4 s = {xa.x + xb.x, xa.y + xb.y, xa.z + xb.z, xa.w + xb.w};
        split_store_a(as_hi, as_lo, m * FAPITCH + k4, s);
    }
    cp_wait0();
    __syncthreads();

    float acc[2][4][4] = {};
    mma_full(ah_u, al_u, bh_u, bl_u, wm, wn, lane, acc);

    #pragma unroll
    for (int mf = 0; mf < 2; ++mf) {
        int r0 = m0 + wm * 32 + mf * 16 + g;
        #pragma unroll
        for (int half = 0; half < 2; ++half) {
            int r = r0 + half * 8;
            int em = g_emask[r] & g_nmask[g_src[r]] & g_nmask[g_dst[r]];
            float fm = em ? 1.0f : 0.0f;
            #pragma unroll
            for (int nf = 0; nf < 4; ++nf) {
                int c = n0 + wn * 32 + nf * 8 + 2 * t;
                float v0 = acc[mf][nf][half * 2 + 0] + bias[c]
                         + fm * efi[(size_t)r * D + c];
                float v1 = acc[mf][nf][half * 2 + 1] + bias[c + 1]
                         + fm * efi[(size_t)r * D + c + 1];
                __nv_bfloat16 h0 = __float2bfloat16(v0), h1 = __float2bfloat16(v1);
                __nv_bfloat16 l0 = __float2bfloat16(v0 - __bfloat162float(h0));
                __nv_bfloat16 l1 = __float2bfloat16(v1 - __bfloat162float(h1));
                *(__nv_bfloat162*)&g_hhi[(size_t)r * D + c] = __nv_bfloat162(h0, h1);
                *(__nv_bfloat162*)&g_hlo[(size_t)r * D + c] = __nv_bfloat162(l0, l1);
            }
        }
    }
}

// fused q/k/v GEMM: A (split h) resident once; loop w with B prefetch overlap
__global__ void __launch_bounds__(256) k_gemm_qkv(
        const float* __restrict__ bq, const float* __restrict__ bk,
        const float* __restrict__ bv) {
    extern __shared__ __nv_bfloat16 smx[];
    uint32_t base = (uint32_t)__cvta_generic_to_shared(smx);
    uint32_t ah_u = base + F_AHI * 2, al_u = base + F_ALO * 2;
    uint32_t bh_u = base + F_BHI * 2, bl_u = base + F_BLO * 2;

    int tid = threadIdx.x;
    int wid = tid >> 5, lane = tid & 31;
    int g = lane >> 2, t = lane & 3;
    int wm = wid >> 1, wn = wid & 1;
    int m0 = blockIdx.y * 128, n0 = blockIdx.x * 64;

    cp_b_full(bh_u, bl_u, 1, n0, tid);   // Wq
    cp_a_full(ah_u, al_u, g_hhi, g_hlo, m0, tid);
    cp_commit();
    cp_wait0();
    __syncthreads();

    #pragma unroll
    for (int w = 0; w < 3; ++w) {
        float acc[2][4][4] = {};
        mma_full(ah_u, al_u, bh_u, bl_u, wm, wn, lane, acc);

        // all warps done reading B -> start async refill for next weight
        if (w < 2) {
            __syncthreads();
            cp_b_full(bh_u, bl_u, 2 + w, n0, tid);  // Wk, then Wv
            cp_commit();
        }

        const float* bias = (w == 0) ? bq : (w == 1) ? bk : bv;
        float* C = (w == 0) ? g_q : (w == 1) ? g_k : g_v;
        #pragma unroll
        for (int mf = 0; mf < 2; ++mf) {
            int r0 = m0 + wm * 32 + mf * 16 + g;
            #pragma unroll
            for (int nf = 0; nf < 4; ++nf) {
                int c = n0 + wn * 32 + nf * 8 + 2 * t;
                float bb0 = bias[c], bb1 = bias[c + 1];
                #pragma unroll
                for (int half = 0; half < 2; ++half) {
                    int r = r0 + half * 8;
                    float2 o2 = {acc[mf][nf][half * 2 + 0] + bb0,
                                 acc[mf][nf][half * 2 + 1] + bb1};
                    *(float2*)&C[(size_t)r * D + c] = o2;
                }
            }
        }
        if (w < 2) {
            cp_wait0();
            __syncthreads();
        }
    }
}

// ================= sparse masked attention =================
__global__ void k_attn() {
    __shared__ int s_cand[MAXC];
    __shared__ float s_sc[HN][MAXC];
    __shared__ int s_n;
    int e = blockIdx.x;
    int tid = threadIdx.x;
    int h = tid >> 5, lane = tid & 31;
    int a = g_src[e], b = g_dst[e];
    int oa = g_off[a];
    int na = g_off[a + 1] - oa;

    for (int i = tid; i < na; i += 128) s_cand[i] = g_inc[oa + i];

    if (tid < 32) {
        int cnt = na;
        if (b != a) {
            int ob = g_off[b];
            int nb = g_off[b + 1] - ob;
            for (int i0 = 0; i0 < nb; i0 += 32) {
                int i = i0 + lane;
                int f = 0, keep = 0;
                if (i < nb) {
                    f = g_inc[ob + i];
                    keep = (g_src[f] != a && g_dst[f] != a) ? 1 : 0;
                }
                unsigned bal = __ballot_sync(0xffffffffu, keep != 0);
                if (keep) {
                    int pos = cnt + __popc(bal & ((1u << lane) - 1u));
                    if (pos < MAXC) s_cand[pos] = f;
                }
                cnt += __popc(bal);
            }
        }
        if (lane == 0) s_n = (cnt < MAXC) ? cnt : MAXC;
    }
    __syncthreads();
    int nc = s_n;
    int base = e * D + h * DHD;

    float2 q2 = *(const float2*)&g_q[base + lane * 2];

    for (int c = 0; c < nc; ++c) {
        int f = s_cand[c];
        float2 k2 = *(const float2*)&g_k[f * D + h * DHD + lane * 2];
        float s = q2.x * k2.x + q2.y * k2.y;
        #pragma unroll
        for (int o = 16; o; o >>= 1) s += __shfl_xor_sync(0xffffffffu, s, o);
        if (lane == 0) s_sc[h][c] = s * 0.125f;
    }
    __syncwarp();

    float mx = -3.0e38f;
    for (int c = lane; c < nc; c += 32) mx = fmaxf(mx, s_sc[h][c]);
    #pragma unroll
    for (int o = 16; o; o >>= 1) mx = fmaxf(mx, __shfl_xor_sync(0xffffffffu, mx, o));
    float l = 0.f;
    for (int c = lane; c < nc; c += 32) {
        float p = __expf(s_sc[h][c] - mx);
        s_sc[h][c] = p;
        l += p;
    }
    #pragma unroll
    for (int o = 16; o; o >>= 1) l += __shfl_xor_sync(0xffffffffu, l, o);
    __syncwarp();

    float ax = 0.f, ay = 0.f;
    for (int c = 0; c < nc; ++c) {
        float p = s_sc[h][c];
        float2 v2 = *(const float2*)&g_v[s_cand[c] * D + h * DHD + lane * 2];
        ax += p * v2.x;
        ay += p * v2.y;
    }
    float inv = 1.f / l;
    float vx = ax * inv, vy = ay * inv;
    __nv_bfloat16 hx = __float2bfloat16(vx), hy = __float2bfloat16(vy);
    __nv_bfloat16 lx = __float2bfloat16(vx - __bfloat162float(hx));
    __nv_bfloat16 ly = __float2bfloat16(vy - __bfloat162float(hy));
    *(__nv_bfloat162*)&g_aohi[base + lane * 2] = __nv_bfloat162(hx, hy);
    *(__nv_bfloat162*)&g_aolo[base + lane * 2] = __nv_bfloat162(lx, ly);
}

// ================= classifier =================
__global__ void k_cls(const float* __restrict__ W2, const float* __restrict__ b2,
                      float* __restrict__ out) {
    int warp = (blockIdx.x * blockDim.x + threadIdx.x) >> 5;
    int lane = threadIdx.x & 31;
    if (warp >= NE) return;
    float x[8];
    #pragma unroll
    for (int i = 0; i < 8; ++i) {
        size_t id = (size_t)warp * D + lane + i * 32;
        x[i] = __bfloat162float(g_hidhi[id]) + __bfloat162float(g_hidlo[id]);
    }
    float res = 0.f;
    #pragma unroll
    for (int c = 0; c < CLS; ++c) {
        float s = 0.f;
        #pragma unroll
        for (int i = 0; i < 8; ++i) s += x[i] * W2[(size_t)(lane + i * 32) * CLS + c];
        #pragma unroll
        for (int o = 16; o; o >>= 1) s += __shfl_xor_sync(0xffffffffu, s, o);
        if (lane == c) res = s + b2[c];
    }
    if (lane < CLS) out[(size_t)warp * CLS + lane] = res;
}

// ================= host =================
extern "C" void kernel_launch(void* const* d_in, const int* in_sizes, int n_in,
                              void* d_out, int out_size) {
    const float* nf   = (const float*)d_in[0];
    const float* efi  = (const float*)d_in[1];
    const int*   ei   = (const int*)d_in[2];
    const float* Wn_r = (const float*)d_in[3];
    const float* bn_r = (const float*)d_in[4];
    const float* We_r = (const float*)d_in[5];
    const float* be_r = (const float*)d_in[6];
    const float* Wnp  = (const float*)d_in[7];
    const float* bnp  = (const float*)d_in[8];
    const float* Wq   = (const float*)d_in[9];
    const float* bq   = (const float*)d_in[10];
    const float* Wk   = (const float*)d_in[11];
    const float* bk   = (const float*)d_in[12];
    const float* Wv   = (const float*)d_in[13];
    const float* bv   = (const float*)d_in[14];
    const float* Wo   = (const float*)d_in[15];
    const float* bo   = (const float*)d_in[16];
    const float* W1   = (const float*)d_in[17];
    const float* b1   = (const float*)d_in[18];
    const float* W2   = (const float*)d_in[19];
    const float* b2   = (const float*)d_in[20];
    float* out = (float*)d_out;

    cudaFuncSetAttribute(k_gemm_h, cudaFuncAttributeMaxDynamicSharedMemorySize, F_BYTES);
    cudaFuncSetAttribute(k_gemm_qkv, cudaFuncAttributeMaxDynamicSharedMemorySize, F_BYTES);
    cudaFuncSetAttribute(k_gemm_sp<0, 1, 2>, cudaFuncAttributeMaxDynamicSharedMemorySize, F_BYTES);
    cudaFuncSetAttribute(k_gemm_sp<1, 2, 3>, cudaFuncAttributeMaxDynamicSharedMemorySize, F_BYTES);

    k_front<<<752, 256>>>(nf, efi, ei, Wn_r, bn_r, We_r, be_r, Wnp, Wq, Wk, Wv, Wo, W1);
    k_build<<<3, 1024>>>();

    dim3 gg(D / 64, NE / 128);      // (4, 32) = 128 CTAs <= 148 SMs: one wave
    k_gemm_h<<<gg, 256, F_BYTES>>>(nf, efi, bnp);            // h (split)
    k_gemm_qkv<<<gg, 256, F_BYTES>>>(bq, bk, bv);            // q,k,v fp32 (A resident x3)
    k_attn<<<NE, 128>>>();                                   // ao (split)
    k_gemm_sp<0, 1, 2><<<gg, 256, F_BYTES>>>(4, bo);         // o (split)
    k_gemm_sp<1, 2, 3><<<gg, 256, F_BYTES>>>(5, b1);         // hid (split)
    k_cls<<<(NE * 32 + 255) / 256, 256>>>(W2, b2, out);
}

// round 12
// speedup vs baseline: 1.0831x; 1.0313x over previous
#include <cuda_runtime.h>
#include <cuda_bf16.h>
#include <math.h>
#include <stdint.h>

#define NN    1024
#define NE    4096
#define D     256
#define HN    4
#define DHD   64
#define NODEK 512
#define EDGEK 2048
#define CLS   16
#define MAXC  1024

// full-K resident GEMM: CTA 128x64, K=256, 8 warps (4m x 2n), warp 32x32
#define FAPITCH 264
#define F_AHI 0
#define F_ALO (128 * FAPITCH)
#define F_BHI (2 * 128 * FAPITCH)
#define F_BLO (2 * 128 * FAPITCH + 64 * FAPITCH)
#define F_ELEMS (2 * 128 * FAPITCH + 2 * 64 * FAPITCH)
#define F_BYTES (F_ELEMS * 2)   // 202752 B -> 1 CTA/SM (grid = 128 <= 148: one wave)

// ---------------- scratch ----------------
__device__ float g_nscore[NN];
__device__ float g_escore[NE];
__device__ int   g_nmask[NN];
__device__ int   g_emask[NE];
__device__ int   g_src[NE], g_dst[NE];
__device__ int   g_off[NN + 1];
__device__ int   g_inc[2 * NE];
__device__ float g_q[NE * D];
__device__ float g_k[NE * D];
__device__ float g_v[NE * D];
// split-bf16 activations (hi + residual lo)
__device__ __nv_bfloat16 g_hhi[NE * D],   g_hlo[NE * D];    // pair 0
__device__ __nv_bfloat16 g_aohi[NE * D],  g_aolo[NE * D];   // pair 1
__device__ __nv_bfloat16 g_ohi[NE * D],   g_olo[NE * D];    // pair 2
__device__ __nv_bfloat16 g_hidhi[NE * D], g_hidlo[NE * D];  // pair 3
// transposed split-bf16 weights: [w][n][k], w: 0=Wnp 1=Wq 2=Wk 3=Wv 4=Wo 5=W1
__device__ __nv_bfloat16 g_wthi[6 * D * D];
__device__ __nv_bfloat16 g_wtlo[6 * D * D];

template <int ID> __device__ __forceinline__ __nv_bfloat16* bufhi();
template <> __device__ __forceinline__ __nv_bfloat16* bufhi<0>() { return g_hhi; }
template <> __device__ __forceinline__ __nv_bfloat16* bufhi<1>() { return g_aohi; }
template <> __device__ __forceinline__ __nv_bfloat16* bufhi<2>() { return g_ohi; }
template <> __device__ __forceinline__ __nv_bfloat16* bufhi<3>() { return g_hidhi; }
template <int ID> __device__ __forceinline__ __nv_bfloat16* buflo();
template <> __device__ __forceinline__ __nv_bfloat16* buflo<0>() { return g_hlo; }
template <> __device__ __forceinline__ __nv_bfloat16* buflo<1>() { return g_aolo; }
template <> __device__ __forceinline__ __nv_bfloat16* buflo<2>() { return g_olo; }
template <> __device__ __forceinline__ __nv_bfloat16* buflo<3>() { return g_hidlo; }

// ================= 1: fused front-end =================
__global__ void k_front(const float* __restrict__ nf, const float* __restrict__ efi,
                        const int* __restrict__ ei,
                        const float* __restrict__ Wn, const float* __restrict__ bn,
                        const float* __restrict__ We, const float* __restrict__ be,
                        const float* __restrict__ Wnp, const float* __restrict__ Wq,
                        const float* __restrict__ Wk, const float* __restrict__ Wv,
                        const float* __restrict__ Wo, const float* __restrict__ W1) {
    int b = blockIdx.x;
    int tid = threadIdx.x;
    if (b < 96) {
        __shared__ float s[64][65];
        int w = b >> 4, t16 = b & 15;
        const float* W;
        switch (w) {
            case 0: W = Wnp; break;
            case 1: W = Wq; break;
            case 2: W = Wk; break;
            case 3: W = Wv; break;
            case 4: W = Wo; break;
            default: W = W1; break;
        }
        int n0 = (t16 & 3) * 64, k0 = (t16 >> 2) * 64;
        int n4 = (tid & 15) * 4, kr = tid >> 4;
        #pragma unroll
        for (int kk = kr; kk < 64; kk += 16) {
            float4 v = *(const float4*)&W[(size_t)(k0 + kk) * D + n0 + n4];
            s[kk][n4] = v.x;
            s[kk][n4 + 1] = v.y;
            s[kk][n4 + 2] = v.z;
            s[kk][n4 + 3] = v.w;
        }
        __syncthreads();
        int nl = tid >> 2, kq = (tid & 3) * 16;
        __nv_bfloat16 hi[16], lo[16];
        #pragma unroll
        for (int i = 0; i < 16; ++i) {
            float x = s[kq + i][nl];
            hi[i] = __float2bfloat16(x);
            lo[i] = __float2bfloat16(x - __bfloat162float(hi[i]));
        }
        size_t off = (size_t)w * D * D + (size_t)(n0 + nl) * D + k0 + kq;
        *(uint4*)&g_wthi[off] = *(uint4*)&hi[0];
        *(uint4*)&g_wthi[off + 8] = *(uint4*)&hi[8];
        *(uint4*)&g_wtlo[off] = *(uint4*)&lo[0];
        *(uint4*)&g_wtlo[off + 8] = *(uint4*)&lo[8];
    } else if (b < 112) {
        __shared__ int sh[256];
        int acc = 0;
        for (int i = tid; i < 2048; i += 256) acc |= ei[2 * i + 1];
        sh[tid] = acc;
        __syncthreads();
        for (int s2 = 128; s2 > 0; s2 >>= 1) {
            if (tid < s2) sh[tid] |= sh[tid + s2];
            __syncthreads();
        }
        int is64 = (sh[0] == 0) ? 1 : 0;
        int i = (b - 96) * 256 + tid;
        int s, d;
        if (is64) { s = ei[2 * i]; d = ei[2 * (NE + i)]; }
        else      { s = ei[i];     d = ei[NE + i]; }
        g_src[i] = s;
        g_dst[i] = d;
    } else {
        int warp = (b - 112) * 8 + (tid >> 5);
        int lane = tid & 31;
        const float* x;
        const float* w;
        if (warp < NN) { x = nf + (size_t)warp * D; w = Wn; }
        else           { x = efi + (size_t)(warp - NN) * D; w = We; }
        float s = 0.f;
        #pragma unroll
        for (int i = 0; i < D / 32; ++i) s += x[lane + i * 32] * w[lane + i * 32];
        #pragma unroll
        for (int o = 16; o; o >>= 1) s += __shfl_xor_sync(0xffffffffu, s, o);
        if (lane == 0) {
            if (warp < NN) g_nscore[warp] = s + bn[0];
            else           g_escore[warp - NN] = s + be[0];
        }
    }
}

// ================= 2: fused build =================
struct TkSmem {
    unsigned su[NE];
    int hist[256];
    unsigned pref;
    int krem;
    int wagg[32];
};
struct IncSmem {
    int cnt[NN];
    int off[NN];
    int pos[NN];
    int inc[2 * NE];
};
union BuildSmem {
    TkSmem tk;
    IncSmem in;
};

__global__ void __launch_bounds__(1024, 1) k_build() {
    __shared__ BuildSmem sm;
    int tid = threadIdx.x;
    int lane = tid & 31, wid = tid >> 5;

    if (blockIdx.x < 2) {
        const bool is_edge = (blockIdx.x == 1);
        const float* sc = is_edge ? g_escore : g_nscore;
        int* mask = is_edge ? g_emask : g_nmask;
        const int n = is_edge ? NE : NN;
        const int kk = is_edge ? EDGEK : NODEK;
        int items = n >> 10;

        for (int j = 0; j < items; ++j) {
            int i = tid * items + j;
            unsigned bb = __float_as_uint(sc[i]);
            sm.tk.su[i] = (bb & 0x80000000u) ? ~bb : (bb | 0x80000000u);
        }
        if (tid == 0) { sm.tk.pref = 0u; sm.tk.krem = kk; }
        __syncthreads();

        for (int shift = 24; shift >= 0; shift -= 8) {
            unsigned prefix = sm.tk.pref;
            unsigned done_mask = (shift == 24) ? 0u : (0xFFFFFFFFu << (shift + 8));
            if (tid < 256) sm.tk.hist[tid] = 0;
            __syncthreads();
            for (int j = 0; j < items; ++j) {
                unsigned u = sm.tk.su[tid * items + j];
                if ((u & done_mask) == prefix)
                    atomicAdd(&sm.tk.hist[(u >> shift) & 255], 1);
            }
            __syncthreads();
            if (wid == 0) {
                int krem = sm.tk.krem;
                int gsum = 0;
                #pragma unroll
                for (int c = 0; c < 8; ++c) gsum += sm.tk.hist[lane * 8 + c];
                int x = gsum;
                #pragma unroll
                for (int off = 1; off < 32; off <<= 1) {
                    int t = __shfl_down_sync(0xffffffffu, x, off);
                    if (lane + off < 32) x += t;
                }
                int above = x - gsum;
                bool hit = (above < krem) && (x >= krem);
                unsigned bal = __ballot_sync(0xffffffffu, hit);
                int srcl = __ffs(bal) - 1;
                if (lane == srcl) {
                    int cum = above;
                    #pragma unroll
                    for (int c = 7; c >= 0; --c) {
                        int bb = lane * 8 + c;
                        int hc = sm.tk.hist[bb];
                        if (cum + hc >= krem) {
                            sm.tk.pref = prefix | ((unsigned)bb << shift);
                            sm.tk.krem = krem - cum;
                            break;
                        }
                        cum += hc;
                    }
                }
            }
            __syncthreads();
        }
        unsigned T = sm.tk.pref;
        int r = sm.tk.krem;

        int ct = 0;
        for (int j = 0; j < items; ++j) ct += (sm.tk.su[tid * items + j] == T) ? 1 : 0;
        int scan = ct;
        #pragma unroll
        for (int off = 1; off < 32; off <<= 1) {
            int t = __shfl_up_sync(0xffffffffu, scan, off);
            if (lane >= off) scan += t;
        }
        if (lane == 31) sm.tk.wagg[wid] = scan;
        __syncthreads();
        if (wid == 0) {
            int v = sm.tk.wagg[lane];
            #pragma unroll
            for (int off = 1; off < 32; off <<= 1) {
                int t = __shfl_up_sync(0xffffffffu, v, off);
                if (lane >= off) v += t;
            }
            sm.tk.wagg[lane] = v;
        }
        __syncthreads();
        int excl = (wid > 0 ? sm.tk.wagg[wid - 1] : 0) + scan - ct;

        for (int j = 0; j < items; ++j) {
            int i = tid * items + j;
            unsigned u = sm.tk.su[i];
            int mk;
            if (u > T) mk = 1;
            else if (u == T) { mk = (excl < r) ? 1 : 0; excl++; }
            else mk = 0;
            mask[i] = mk;
        }
    } else {
        sm.in.cnt[tid] = 0;
        __syncthreads();
        #pragma unroll
        for (int j = 0; j < 4; ++j) {
            int e = j * 1024 + tid;
            int a = g_src[e], b = g_dst[e];
            atomicAdd(&sm.in.cnt[a], 1);
            if (b != a) atomicAdd(&sm.in.cnt[b], 1);
        }
        __syncthreads();
        int own = sm.in.cnt[tid];
        int val = own;
        for (int dd = 1; dd < 1024; dd <<= 1) {
            int t = (tid >= dd) ? sm.in.cnt[tid - dd] : 0;
            __syncthreads();
            val += t;
            sm.in.cnt[tid] = val;
            __syncthreads();
        }
        int offv = val - own;
        sm.in.off[tid] = offv;
        sm.in.pos[tid] = offv;
        if (tid == 1023) g_off[1024] = val;
        g_off[tid] = offv;
        __syncthreads();
        int total = sm.in.cnt[1023];
        #pragma unroll
        for (int j = 0; j < 4; ++j) {
            int e = j * 1024 + tid;
            int a = g_src[e], b = g_dst[e];
            sm.in.inc[atomicAdd(&sm.in.pos[a], 1)] = e;
            if (b != a) sm.in.inc[atomicAdd(&sm.in.pos[b], 1)] = e;
        }
        __syncthreads();
        {
            int s = sm.in.off[tid];
            int t = sm.in.pos[tid];
            for (int i = s + 1; i < t; ++i) {
                int v = sm.in.inc[i];
                int j = i - 1;
                while (j >= s && sm.in.inc[j] > v) { sm.in.inc[j + 1] = sm.in.inc[j]; --j; }
                sm.in.inc[j + 1] = v;
            }
        }
        __syncthreads();
        for (int i = tid; i < total; i += 1024) g_inc[i] = sm.in.inc[i];
    }
}

// ================= GEMM primitives =================
__device__ __forceinline__ void mma_bf16(float* c, const uint32_t* a, const uint32_t* b) {
    asm volatile(
        "mma.sync.aligned.m16n8k16.row.col.f32.bf16.bf16.f32 "
        "{%0,%1,%2,%3}, {%4,%5,%6,%7}, {%8,%9}, {%0,%1,%2,%3};"
        : "+f"(c[0]), "+f"(c[1]), "+f"(c[2]), "+f"(c[3])
        : "r"(a[0]), "r"(a[1]), "r"(a[2]), "r"(a[3]), "r"(b[0]), "r"(b[1]));
}

__device__ __forceinline__ void ldm_x4(uint32_t* r, uint32_t addr) {
    asm volatile("ldmatrix.sync.aligned.m8n8.x4.shared.b16 {%0,%1,%2,%3}, [%4];"
                 : "=r"(r[0]), "=r"(r[1]), "=r"(r[2]), "=r"(r[3]) : "r"(addr));
}

__device__ __forceinline__ void cp16(uint32_t s, const void* g) {
    asm volatile("cp.async.cg.shared.global [%0], [%1], 16;" :: "r"(s), "l"(g));
}
__device__ __forceinline__ void cp_commit() {
    asm volatile("cp.async.commit_group;" ::: "memory");
}
__device__ __forceinline__ void cp_wait0() {
    asm volatile("cp.async.wait_group 0;" ::: "memory");
}
__device__ __forceinline__ void cp_wait1() {
    asm volatile("cp.async.wait_group 1;" ::: "memory");
}

__device__ __forceinline__ void split_store_a(__nv_bfloat16* as_hi, __nv_bfloat16* as_lo,
                                              int o, float4 a) {
    __nv_bfloat16 h0 = __float2bfloat16(a.x), h1 = __float2bfloat16(a.y);
    __nv_bfloat16 h2 = __float2bfloat16(a.z), h3 = __float2bfloat16(a.w);
    __nv_bfloat16 l0 = __float2bfloat16(a.x - __bfloat162float(h0));
    __nv_bfloat16 l1 = __float2bfloat16(a.y - __bfloat162float(h1));
    __nv_bfloat16 l2 = __float2bfloat16(a.z - __bfloat162float(h2));
    __nv_bfloat16 l3 = __float2bfloat16(a.w - __bfloat162float(h3));
    *(__nv_bfloat162*)&as_hi[o]     = __nv_bfloat162(h0, h1);
    *(__nv_bfloat162*)&as_hi[o + 2] = __nv_bfloat162(h2, h3);
    *(__nv_bfloat162*)&as_lo[o]     = __nv_bfloat162(l0, l1);
    *(__nv_bfloat162*)&as_lo[o + 2] = __nv_bfloat162(l2, l3);
}

// async copy A half [128 x 128] (hi+lo): kh selects k in [kh*128, kh*128+128)
__device__ __forceinline__ void cp_a_half(uint32_t ah_u, uint32_t al_u,
                                          const __nv_bfloat16* Ahi, const __nv_bfloat16* Alo,
                                          int m0, int tid, int kh) {
    int kb = kh * 128;
    #pragma unroll
    for (int it = 0; it < 8; ++it) {
        int idx = it * 256 + tid;            // 2048 16B chunks per array per half
        int m = idx >> 4, kq = kb + (idx & 15) * 8;
        uint32_t so = (uint32_t)((m * FAPITCH + kq) * 2);
        cp16(ah_u + so, &Ahi[(size_t)(m0 + m) * D + kq]);
        cp16(al_u + so, &Alo[(size_t)(m0 + m) * D + kq]);
    }
}

// async copy B [64 x 256] (hi+lo) for weight wslot
__device__ __forceinline__ void cp_b_full(uint32_t bh_u, uint32_t bl_u,
                                          int wslot, int n0, int tid) {
    const __nv_bfloat16* Bh = g_wthi + (size_t)wslot * D * D;
    const __nv_bfloat16* Bl = g_wtlo + (size_t)wslot * D * D;
    #pragma unroll
    for (int it = 0; it < 8; ++it) {
        int idx = it * 256 + tid;            // 2048 16B chunks per array
        int n = idx >> 5, kq = (idx & 31) * 8;
        uint32_t so = (uint32_t)((n * FAPITCH + kq) * 2);
        cp16(bh_u + so, &Bh[(size_t)(n0 + n) * D + kq]);
        cp16(bl_u + so, &Bl[(size_t)(n0 + n) * D + kq]);
    }
}

// mma over k-steps [ks0, ks0+nks): 8 ldmatrix.x4 : 24 HMMA per step
__device__ __forceinline__ void mma_steps(uint32_t ah_u, uint32_t al_u,
                                          uint32_t bh_u, uint32_t bl_u,
                                          int wm, int wn, int lane,
                                          int ks0, int nks, float acc[2][4][4]) {
    int a_row = wm * 32 + (lane & 15);
    int a_ko = (lane >> 4) << 3;
    uint32_t aoff0 = (uint32_t)((a_row * FAPITCH + a_ko) * 2);
    uint32_t aoff1 = (uint32_t)(((a_row + 16) * FAPITCH + a_ko) * 2);
    int b_row = wn * 32 + (lane & 7) + ((lane >> 4) << 3);
    int b_ko = ((lane >> 3) & 1) << 3;
    uint32_t boff0 = (uint32_t)((b_row * FAPITCH + b_ko) * 2);
    uint32_t boff1 = (uint32_t)(((b_row + 16) * FAPITCH + b_ko) * 2);
    #pragma unroll
    for (int s = 0; s < 8; ++s) {
        if (s >= nks) break;
        uint32_t kb2 = (uint32_t)((ks0 + s) * 32);
        uint32_t ah[2][4], al[2][4], bh[2][4], bl[2][4];
        ldm_x4(ah[0], ah_u + aoff0 + kb2);
        ldm_x4(ah[1], ah_u + aoff1 + kb2);
        ldm_x4(al[0], al_u + aoff0 + kb2);
        ldm_x4(al[1], al_u + aoff1 + kb2);
        ldm_x4(bh[0], bh_u + boff0 + kb2);
        ldm_x4(bh[1], bh_u + boff1 + kb2);
        ldm_x4(bl[0], bl_u + boff0 + kb2);
        ldm_x4(bl[1], bl_u + boff1 + kb2);
        #pragma unroll
        for (int mf = 0; mf < 2; ++mf)
            #pragma unroll
            for (int nf = 0; nf < 4; ++nf) {
                const uint32_t* bhp = &bh[nf >> 1][(nf & 1) * 2];
                const uint32_t* blp = &bl[nf >> 1][(nf & 1) * 2];
                mma_bf16(acc[mf][nf], ah[mf], bhp);
                mma_bf16(acc[mf][nf], ah[mf], blp);
                mma_bf16(acc[mf][nf], al[mf], bhp);
            }
    }
}

// ================= GEMM kernels =================
// generic split->split, 2-stage pipelined prologue
template <int ACT, int AID, int CID>
__global__ void __launch_bounds__(256) k_gemm_sp(int wslot, const float* __restrict__ bias) {
    extern __shared__ __nv_bfloat16 smx[];
    uint32_t base = (uint32_t)__cvta_generic_to_shared(smx);
    uint32_t ah_u = base + F_AHI * 2, al_u = base + F_ALO * 2;
    uint32_t bh_u = base + F_BHI * 2, bl_u = base + F_BLO * 2;

    int tid = threadIdx.x;
    int wid = tid >> 5, lane = tid & 31;
    int g = lane >> 2, t = lane & 3;
    int wm = wid >> 1, wn = wid & 1;
    int m0 = blockIdx.y * 128, n0 = blockIdx.x * 64;

    // group0: B + A[k<128]; group1: A[k>=128]
    cp_b_full(bh_u, bl_u, wslot, n0, tid);
    cp_a_half(ah_u, al_u, bufhi<AID>(), buflo<AID>(), m0, tid, 0);
    cp_commit();
    cp_a_half(ah_u, al_u, bufhi<AID>(), buflo<AID>(), m0, tid, 1);
    cp_commit();

    float acc[2][4][4] = {};
    cp_wait1();
    __syncthreads();
    mma_steps(ah_u, al_u, bh_u, bl_u, wm, wn, lane, 0, 8, acc);
    cp_wait0();
    __syncthreads();
    mma_steps(ah_u, al_u, bh_u, bl_u, wm, wn, lane, 8, 8, acc);

    __nv_bfloat16* Chi = bufhi<CID>();
    __nv_bfloat16* Clo = buflo<CID>();
    #pragma unroll
    for (int mf = 0; mf < 2; ++mf) {
        int r0 = m0 + wm * 32 + mf * 16 + g;
        #pragma unroll
        for (int nf = 0; nf < 4; ++nf) {
            int c = n0 + wn * 32 + nf * 8 + 2 * t;
            float bb0 = bias[c], bb1 = bias[c + 1];
            #pragma unroll
            for (int half = 0; half < 2; ++half) {
                int r = r0 + half * 8;
                float v0 = acc[mf][nf][half * 2 + 0] + bb0;
                float v1 = acc[mf][nf][half * 2 + 1] + bb1;
                if (ACT == 1) {
                    float x0 = v0, x1 = v1;
                    float t0 = tanhf(0.7978845608028654f * (x0 + 0.044715f * x0 * x0 * x0));
                    float t1 = tanhf(0.7978845608028654f * (x1 + 0.044715f * x1 * x1 * x1));
                    v0 = 0.5f * x0 * (1.0f + t0);
                    v1 = 0.5f * x1 * (1.0f + t1);
                }
                __nv_bfloat16 h0 = __float2bfloat16(v0), h1 = __float2bfloat16(v1);
                __nv_bfloat16 l0 = __float2bfloat16(v0 - __bfloat162float(h0));
                __nv_bfloat16 l1 = __float2bfloat16(v1 - __bfloat162float(h1));
                *(__nv_bfloat162*)&Chi[(size_t)r * D + c] = __nv_bfloat162(h0, h1);
                *(__nv_bfloat162*)&Clo[(size_t)r * D + c] = __nv_bfloat162(l0, l1);
            }
        }
    }
}

// h GEMM: A computed on the fly (nf[src]+nf[dst]); B loads async behind it
__global__ void __launch_bounds__(256) k_gemm_h(const float* __restrict__ nf,
                                                const float* __restrict__ efi,
                                                const float* __restrict__ bias) {
    extern __shared__ __nv_bfloat16 smx[];
    __nv_bfloat16* as_hi = smx + F_AHI;
    __nv_bfloat16* as_lo = smx + F_ALO;
    uint32_t base = (uint32_t)__cvta_generic_to_shared(smx);
    uint32_t ah_u = base + F_AHI * 2, al_u = base + F_ALO * 2;
    uint32_t bh_u = base + F_BHI * 2, bl_u = base + F_BLO * 2;

    int tid = threadIdx.x;
    int wid = tid >> 5, lane = tid & 31;
    int g = lane >> 2, t = lane & 3;
    int wm = wid >> 1, wn = wid & 1;
    int m0 = blockIdx.y * 128, n0 = blockIdx.x * 64;

    cp_b_full(bh_u, bl_u, 0, n0, tid);
    cp_commit();
    #pragma unroll
    for (int it = 0; it < 32; ++it) {
        int idx = it * 256 + tid;        // 8192 float4
        int m = idx >> 6, k4 = (idx & 63) * 4;
        int e = m0 + m;
        int a = g_src[e], b = g_dst[e];
        float4 xa = *(const float4*)&nf[(size_t)a * D + k4];
        float4 xb = *(const float4*)&nf[(size_t)b * D + k4];
        float4 s = {xa.x + xb.x, xa.y + xb.y, xa.z + xb.z, xa.w + xb.w};
        split_store_a(as_hi, as_lo, m * FAPITCH + k4, s);
    }
    cp_wait0();
    __syncthreads();

    float acc[2][4][4] = {};
    mma_steps(ah_u, al_u, bh_u, bl_u, wm, wn, lane, 0, 8, acc);
    mma_steps(ah_u, al_u, bh_u, bl_u, wm, wn, lane, 8, 8, acc);

    #pragma unroll
    for (int mf = 0; mf < 2; ++mf) {
        int r0 = m0 + wm * 32 + mf * 16 + g;
        #pragma unroll
        for (int half = 0; half < 2; ++half) {
            int r = r0 + half * 8;
            int em = g_emask[r] & g_nmask[g_src[r]] & g_nmask[g_dst[r]];
            float fm = em ? 1.0f : 0.0f;
            #pragma unroll
            for (int nf = 0; nf < 4; ++nf) {
                int c = n0 + wn * 32 + nf * 8 + 2 * t;
                float v0 = acc[mf][nf][half * 2 + 0] + bias[c]
                         + fm * efi[(size_t)r * D + c];
                float v1 = acc[mf][nf][half * 2 + 1] + bias[c + 1]
                         + fm * efi[(size_t)r * D + c + 1];
                __nv_bfloat16 h0 = __float2bfloat16(v0), h1 = __float2bfloat16(v1);
                __nv_bfloat16 l0 = __float2bfloat16(v0 - __bfloat162float(h0));
                __nv_bfloat16 l1 = __float2bfloat16(v1 - __bfloat162float(h1));
                *(__nv_bfloat162*)&g_hhi[(size_t)r * D + c] = __nv_bfloat162(h0, h1);
                *(__nv_bfloat162*)&g_hlo[(size_t)r * D + c] = __nv_bfloat162(l0, l1);
            }
        }
    }
}

// fused q/k/v GEMM: A resident once; B(w+1) prefetch overlaps epilogue(w)
__global__ void __launch_bounds__(256) k_gemm_qkv(
        const float* __restrict__ bq, const float* __restrict__ bk,
        const float* __restrict__ bv) {
    extern __shared__ __nv_bfloat16 smx[];
    uint32_t base = (uint32_t)__cvta_generic_to_shared(smx);
    uint32_t ah_u = base + F_AHI * 2, al_u = base + F_ALO * 2;
    uint32_t bh_u = base + F_BHI * 2, bl_u = base + F_BLO * 2;

    int tid = threadIdx.x;
    int wid = tid >> 5, lane = tid & 31;
    int g = lane >> 2, t = lane & 3;
    int wm = wid >> 1, wn = wid & 1;
    int m0 = blockIdx.y * 128, n0 = blockIdx.x * 64;

    // group0: B(Wq) + A[k<128]; group1: A[k>=128]
    cp_b_full(bh_u, bl_u, 1, n0, tid);
    cp_a_half(ah_u, al_u, g_hhi, g_hlo, m0, tid, 0);
    cp_commit();
    cp_a_half(ah_u, al_u, g_hhi, g_hlo, m0, tid, 1);
    cp_commit();

    #pragma unroll
    for (int w = 0; w < 3; ++w) {
        float acc[2][4][4] = {};
        if (w == 0) {
            cp_wait1();
            __syncthreads();
            mma_steps(ah_u, al_u, bh_u, bl_u, wm, wn, lane, 0, 8, acc);
            cp_wait0();
            __syncthreads();
            mma_steps(ah_u, al_u, bh_u, bl_u, wm, wn, lane, 8, 8, acc);
        } else {
            mma_steps(ah_u, al_u, bh_u, bl_u, wm, wn, lane, 0, 8, acc);
            mma_steps(ah_u, al_u, bh_u, bl_u, wm, wn, lane, 8, 8, acc);
        }

        if (w < 2) {
            __syncthreads();  // all warps done reading B
            cp_b_full(bh_u, bl_u, 2 + w, n0, tid);
            cp_commit();
        }

        const float* bias = (w == 0) ? bq : (w == 1) ? bk : bv;
        float* C = (w == 0) ? g_q : (w == 1) ? g_k : g_v;
        #pragma unroll
        for (int mf = 0; mf < 2; ++mf) {
            int r0 = m0 + wm * 32 + mf * 16 + g;
            #pragma unroll
            for (int nf = 0; nf < 4; ++nf) {
                int c = n0 + wn * 32 + nf * 8 + 2 * t;
                float bb0 = bias[c], bb1 = bias[c + 1];
                #pragma unroll
                for (int half = 0; half < 2; ++half) {
                    int r = r0 + half * 8;
                    float2 o2 = {acc[mf][nf][half * 2 + 0] + bb0,
                                 acc[mf][nf][half * 2 + 1] + bb1};
                    *(float2*)&C[(size_t)r * D + c] = o2;
                }
            }
        }
        if (w < 2) {
            cp_wait0();
            __syncthreads();
        }
    }
}

// ================= sparse masked attention (2-way ILP) =================
__global__ void k_attn() {
    __shared__ int s_cand[MAXC];
    __shared__ float s_sc[HN][MAXC];
    __shared__ int s_n;
    int e = blockIdx.x;
    int tid = threadIdx.x;
    int h = tid >> 5, lane = tid & 31;
    int a = g_src[e], b = g_dst[e];
    int oa = g_off[a];
    int na = g_off[a + 1] - oa;

    for (int i = tid; i < na; i += 128) s_cand[i] = g_inc[oa + i];

    if (tid < 32) {
        int cnt = na;
        if (b != a) {
            int ob = g_off[b];
            int nb = g_off[b + 1] - ob;
            for (int i0 = 0; i0 < nb; i0 += 32) {
                int i = i0 + lane;
                int f = 0, keep = 0;
                if (i < nb) {
                    f = g_inc[ob + i];
                    keep = (g_src[f] != a && g_dst[f] != a) ? 1 : 0;
                }
                unsigned bal = __ballot_sync(0xffffffffu, keep != 0);
                if (keep) {
                    int pos = cnt + __popc(bal & ((1u << lane) - 1u));
                    if (pos < MAXC) s_cand[pos] = f;
                }
                cnt += __popc(bal);
            }
        }
        if (lane == 0) s_n = (cnt < MAXC) ? cnt : MAXC;
    }
    __syncthreads();
    int nc = s_n;
    int base = e * D + h * DHD;

    float2 q2 = *(const float2*)&g_q[base + lane * 2];

    // scores: two candidates per iteration (interleaved loads + reductions)
    for (int c = 0; c < nc; c += 2) {
        int f0 = s_cand[c];
        float2 k0 = *(const float2*)&g_k[f0 * D + h * DHD + lane * 2];
        bool has1 = (c + 1 < nc);
        float2 k1 = {0.f, 0.f};
        if (has1) {
            int f1 = s_cand[c + 1];
            k1 = *(const float2*)&g_k[f1 * D + h * DHD + lane * 2];
        }
        float s0 = q2.x * k0.x + q2.y * k0.y;
        float s1 = q2.x * k1.x + q2.y * k1.y;
        #pragma unroll
        for (int o = 16; o; o >>= 1) {
            s0 += __shfl_xor_sync(0xffffffffu, s0, o);
            s1 += __shfl_xor_sync(0xffffffffu, s1, o);
        }
        if (lane == 0) {
            s_sc[h][c] = s0 * 0.125f;
            if (has1) s_sc[h][c + 1] = s1 * 0.125f;
        }
    }
    __syncwarp();

    float mx = -3.0e38f;
    for (int c = lane; c < nc; c += 32) mx = fmaxf(mx, s_sc[h][c]);
    #pragma unroll
    for (int o = 16; o; o >>= 1) mx = fmaxf(mx, __shfl_xor_sync(0xffffffffu, mx, o));
    float l = 0.f;
    for (int c = lane; c < nc; c += 32) {
        float p = __expf(s_sc[h][c] - mx);
        s_sc[h][c] = p;
        l += p;
    }
    #pragma unroll
    for (int o = 16; o; o >>= 1) l += __shfl_xor_sync(0xffffffffu, l, o);
    __syncwarp();

    // weighted V sum: two candidates per iteration
    float ax = 0.f, ay = 0.f;
    for (int c = 0; c < nc; c += 2) {
        float p0 = s_sc[h][c];
        float2 v0 = *(const float2*)&g_v[s_cand[c] * D + h * DHD + lane * 2];
        if (c + 1 < nc) {
            float p1 = s_sc[h][c + 1];
            float2 v1 = *(const float2*)&g_v[s_cand[c + 1] * D + h * DHD + lane * 2];
            ax += p0 * v0.x + p1 * v1.x;
            ay += p0 * v0.y + p1 * v1.y;
        } else {
            ax += p0 * v0.x;
            ay += p0 * v0.y;
        }
    }
    float inv = 1.f / l;
    float vx = ax * inv, vy = ay * inv;
    __nv_bfloat16 hx = __float2bfloat16(vx), hy = __float2bfloat16(vy);
    __nv_bfloat16 lx = __float2bfloat16(vx - __bfloat162float(hx));
    __nv_bfloat16 ly = __float2bfloat16(vy - __bfloat162float(hy));
    *(__nv_bfloat162*)&g_aohi[base + lane * 2] = __nv_bfloat162(hx, hy);
    *(__nv_bfloat162*)&g_aolo[base + lane * 2] = __nv_bfloat162(lx, ly);
}

// ================= classifier =================
__global__ void k_cls(const float* __restrict__ W2, const float* __restrict__ b2,
                      float* __restrict__ out) {
    int warp = (blockIdx.x * blockDim.x + threadIdx.x) >> 5;
    int lane = threadIdx.x & 31;
    if (warp >= NE) return;
    float x[8];
    #pragma unroll
    for (int i = 0; i < 8; ++i) {
        size_t id = (size_t)warp * D + lane + i * 32;
        x[i] = __bfloat162float(g_hidhi[id]) + __bfloat162float(g_hidlo[id]);
    }
    float res = 0.f;
    #pragma unroll
    for (int c = 0; c < CLS; ++c) {
        float s = 0.f;
        #pragma unroll
        for (int i = 0; i < 8; ++i) s += x[i] * W2[(size_t)(lane + i * 32) * CLS + c];
        #pragma unroll
        for (int o = 16; o; o >>= 1) s += __shfl_xor_sync(0xffffffffu, s, o);
        if (lane == c) res = s + b2[c];
    }
    if (lane < CLS) out[(size_t)warp * CLS + lane] = res;
}

// ================= host =================
extern "C" void kernel_launch(void* const* d_in, const int* in_sizes, int n_in,
                              void* d_out, int out_size) {
    const float* nf   = (const float*)d_in[0];
    const float* efi  = (const float*)d_in[1];
    const int*   ei   = (const int*)d_in[2];
    const float* Wn_r = (const float*)d_in[3];
    const float* bn_r = (const float*)d_in[4];
    const float* We_r = (const float*)d_in[5];
    const float* be_r = (const float*)d_in[6];
    const float* Wnp  = (const float*)d_in[7];
    const float* bnp  = (const float*)d_in[8];
    const float* Wq   = (const float*)d_in[9];
    const float* bq   = (const float*)d_in[10];
    const float* Wk   = (const float*)d_in[11];
    const float* bk   = (const float*)d_in[12];
    const float* Wv   = (const float*)d_in[13];
    const float* bv   = (const float*)d_in[14];
    const float* Wo   = (const float*)d_in[15];
    const float* bo   = (const float*)d_in[16];
    const float* W1   = (const float*)d_in[17];
    const float* b1   = (const float*)d_in[18];
    const float* W2   = (const float*)d_in[19];
    const float* b2   = (const float*)d_in[20];
    float* out = (float*)d_out;

    cudaFuncSetAttribute(k_gemm_h, cudaFuncAttributeMaxDynamicSharedMemorySize, F_BYTES);
    cudaFuncSetAttribute(k_gemm_qkv, cudaFuncAttributeMaxDynamicSharedMemorySize, F_BYTES);
    cudaFuncSetAttribute(k_gemm_sp<0, 1, 2>, cudaFuncAttributeMaxDynamicSharedMemorySize, F_BYTES);
    cudaFuncSetAttribute(k_gemm_sp<1, 2, 3>, cudaFuncAttributeMaxDynamicSharedMemorySize, F_BYTES);

    k_front<<<752, 256>>>(nf, efi, ei, Wn_r, bn_r, We_r, be_r, Wnp, Wq, Wk, Wv, Wo, W1);
    k_build<<<3, 1024>>>();

    dim3 gg(D / 64, NE / 128);      // (4, 32) = 128 CTAs: one wave
    k_gemm_h<<<gg, 256, F_BYTES>>>(nf, efi, bnp);            // h (split)
    k_gemm_qkv<<<gg, 256, F_BYTES>>>(bq, bk, bv);            // q,k,v fp32
    k_attn<<<NE, 128>>>();                                   // ao (split)
    k_gemm_sp<0, 1, 2><<<gg, 256, F_BYTES>>>(4, bo);         // o (split)
    k_gemm_sp<1, 2, 3><<<gg, 256, F_BYTES>>>(5, b1);         // hid (split)
    k_cls<<<(NE * 32 + 255) / 256, 256>>>(W2, b2, out);
}